// round 3
// baseline (speedup 1.0000x reference)
#include <cuda_runtime.h>
#include <cuda_bf16.h>
#include <cstddef>

// Problem constants
#define BB 8
#define TT 64
#define NV 128
#define DD 512
#define KH 8
#define DH 64
#define KSZ 3
#define MM (BB*TT*NV)          // 65536 tokens
#define EPSBN 1e-5f

// ---------------- device scratch (static globals; no cudaMalloc allowed) ----------------
__device__ float g_q [(size_t)MM * DD];
__device__ float g_k [(size_t)MM * DD];
__device__ float g_v [(size_t)MM * DD];
__device__ float g_ao[(size_t)MM * DD];

__device__ float g_wq[KSZ * DD * DD];   // [tap][in][out], BN-scale folded
__device__ float g_wk[KSZ * DD * DD];
__device__ float g_wv[DD * DD];         // [in][out]
__device__ float g_wo[DD * DD];         // [in][out]
__device__ float g_bq[DD];
__device__ float g_bk[DD];

// ---------------- weight repack kernels ----------------
// dst[tap*D*D + in*D + out] = W[(out*D+in)*KS + tap] * g[out]*rsqrt(v[out]+eps)
__global__ void repack_conv(const float* __restrict__ W, const float* __restrict__ g,
                            const float* __restrict__ var, float* __restrict__ dst)
{
    int idx = blockIdx.x * 256 + threadIdx.x;
    if (idx >= KSZ * DD * DD) return;
    int out = idx & (DD - 1);
    int in  = (idx >> 9) & (DD - 1);
    int tap = idx >> 18;
    float scale = g[out] * rsqrtf(var[out] + EPSBN);
    dst[idx] = W[((size_t)out * DD + in) * KSZ + tap] * scale;
}

__global__ void fold_bias(const float* __restrict__ b, const float* __restrict__ g,
                          const float* __restrict__ beta, const float* __restrict__ m,
                          const float* __restrict__ v, float* __restrict__ dst)
{
    int o = blockIdx.x * 256 + threadIdx.x;
    if (o >= DD) return;
    float scale = g[o] * rsqrtf(v[o] + EPSBN);
    dst[o] = (b[o] - m[o]) * scale + beta[o];
}

// dst[in*D + out] = W[out*D + in]
__global__ void repack_lin(const float* __restrict__ W, float* __restrict__ dst)
{
    int idx = blockIdx.x * 256 + threadIdx.x;
    if (idx >= DD * DD) return;
    int out = idx & (DD - 1);
    int in  = idx >> 9;
    dst[idx] = W[(size_t)out * DD + in];
}

// ---------------- fused shifted-GEMM (handles causal conv taps) ----------------
// C[m][n] = sum_tap sum_k A[m - shift(tap)*NV][k] * Bt[tap][k][n]   (+ bias[n])
// shift(tap) = (TAPS==3) ? (2-tap) : 0 ; rows with t < shift contribute zero.
template<int TAPS>
__global__ void __launch_bounds__(256) gemm_conv(
    const float* __restrict__ A, const float* __restrict__ Bt,
    const float* __restrict__ bias, float* __restrict__ C)
{
    __shared__ float As[8][128];
    __shared__ float Bs[8][128];
    const int bm = blockIdx.y * 128;
    const int bn = blockIdx.x * 128;
    const int tid = threadIdx.x;
    const int tx = tid & 15, ty = tid >> 4;

    float acc[8][8];
#pragma unroll
    for (int i = 0; i < 8; i++)
#pragma unroll
        for (int j = 0; j < 8; j++) acc[i][j] = 0.f;

    const int arow = tid >> 1;          // 0..127
    const int acol = (tid & 1) * 4;     // 0 or 4
    const int brow = tid >> 5;          // 0..7
    const int bcol = (tid & 31) * 4;    // 0..124

    const int m = bm + arow;
    const int t = (m >> 7) & (TT - 1);  // (m/NV)%TT

#pragma unroll
    for (int tap = 0; tap < TAPS; ++tap) {
        const int s = (TAPS == 3) ? (2 - tap) : 0;
        const bool valid = (t >= s);
        const float* Arow = A + (size_t)(m - s * NV) * DD;
        const float* Bt_t = Bt + (size_t)tap * DD * DD;
        for (int k0 = 0; k0 < DD; k0 += 8) {
            float4 av = valid ? *(const float4*)(Arow + k0 + acol)
                              : make_float4(0.f, 0.f, 0.f, 0.f);
            As[acol + 0][arow] = av.x;
            As[acol + 1][arow] = av.y;
            As[acol + 2][arow] = av.z;
            As[acol + 3][arow] = av.w;
            *(float4*)&Bs[brow][bcol] =
                *(const float4*)(Bt_t + (size_t)(k0 + brow) * DD + bn + bcol);
            __syncthreads();
#pragma unroll
            for (int kk = 0; kk < 8; ++kk) {
                float a[8], b[8];
#pragma unroll
                for (int i = 0; i < 4; i++) {
                    a[i]     = As[kk][ty * 4 + i];
                    a[4 + i] = As[kk][64 + ty * 4 + i];
                }
#pragma unroll
                for (int j = 0; j < 4; j++) {
                    b[j]     = Bs[kk][tx * 4 + j];
                    b[4 + j] = Bs[kk][64 + tx * 4 + j];
                }
#pragma unroll
                for (int i = 0; i < 8; i++)
#pragma unroll
                    for (int j = 0; j < 8; j++)
                        acc[i][j] += a[i] * b[j];
            }
            __syncthreads();
        }
    }

#pragma unroll
    for (int i = 0; i < 8; i++) {
        int r = (i < 4) ? (ty * 4 + i) : (64 + ty * 4 + (i - 4));
        float* Crow = C + (size_t)(bm + r) * DD + bn;
#pragma unroll
        for (int jj = 0; jj < 2; jj++) {
            int c0 = jj * 64 + tx * 4;
            float4 o;
            o.x = acc[i][jj * 4 + 0] + bias[bn + c0 + 0];
            o.y = acc[i][jj * 4 + 1] + bias[bn + c0 + 1];
            o.z = acc[i][jj * 4 + 2] + bias[bn + c0 + 2];
            o.w = acc[i][jj * 4 + 3] + bias[bn + c0 + 3];
            *(float4*)(Crow + c0) = o;
        }
    }
}

// ---------------- attention: one block per (b, n, h) head; T=64, DH=64 ----------------
// dynamic smem: Qt[64][65] (also reused as Ss), Kt[64][65], Vs[64][64]
__global__ void __launch_bounds__(256) attn_kernel(
    const float* __restrict__ Q, const float* __restrict__ K,
    const float* __restrict__ V, float* __restrict__ O)
{
    extern __shared__ float sm[];
    float* Qt = sm;                 // pitch 65; later reused as softmax matrix Ss
    float* Kt = sm + 64 * 65;       // pitch 65
    float* Vs = sm + 2 * 64 * 65;   // pitch 64

    const int tid = threadIdx.x;
    const int hid = blockIdx.x;
    const int h = hid & 7;
    const int n = (hid >> 3) & 127;
    const int b = hid >> 10;
    const size_t base = (((size_t)b * TT) * NV + n) * DD + h * DH;
    const size_t rstride = (size_t)NV * DD;   // 65536

    // load Q,K transposed (d-major) and V natural
    {
        int row = tid >> 2;           // t: 0..63
        int c0  = (tid & 3) * 16;     // d base
        const float* qr = Q + base + (size_t)row * rstride;
        const float* kr = K + base + (size_t)row * rstride;
        const float* vr = V + base + (size_t)row * rstride;
#pragma unroll
        for (int u = 0; u < 4; ++u) {
            int d0 = c0 + u * 4;
            float4 qv = *(const float4*)(qr + d0);
            float4 kv = *(const float4*)(kr + d0);
            float4 vv = *(const float4*)(vr + d0);
            Qt[(d0 + 0) * 65 + row] = qv.x;
            Qt[(d0 + 1) * 65 + row] = qv.y;
            Qt[(d0 + 2) * 65 + row] = qv.z;
            Qt[(d0 + 3) * 65 + row] = qv.w;
            Kt[(d0 + 0) * 65 + row] = kv.x;
            Kt[(d0 + 1) * 65 + row] = kv.y;
            Kt[(d0 + 2) * 65 + row] = kv.z;
            Kt[(d0 + 3) * 65 + row] = kv.w;
            *(float4*)&Vs[row * 64 + d0] = vv;
        }
    }
    __syncthreads();

    const int tx = tid & 15, ty = tid >> 4;

    // S = Q K^T * DH^-0.5   (each thread: 4x4 tile)
    float s[4][4];
#pragma unroll
    for (int i = 0; i < 4; i++)
#pragma unroll
        for (int j = 0; j < 4; j++) s[i][j] = 0.f;

    for (int kk = 0; kk < 64; ++kk) {
        float a[4], bb[4];
#pragma unroll
        for (int i = 0; i < 4; i++) a[i]  = Qt[kk * 65 + ty * 4 + i];
#pragma unroll
        for (int j = 0; j < 4; j++) bb[j] = Kt[kk * 65 + tx * 4 + j];
#pragma unroll
        for (int i = 0; i < 4; i++)
#pragma unroll
            for (int j = 0; j < 4; j++) s[i][j] += a[i] * bb[j];
    }
    __syncthreads();   // everyone done reading Qt before reuse as Ss

#pragma unroll
    for (int i = 0; i < 4; i++)
#pragma unroll
        for (int j = 0; j < 4; j++)
            Qt[(ty * 4 + i) * 65 + tx * 4 + j] = s[i][j] * 0.125f;
    __syncthreads();

    // row-wise softmax (one thread per row, T=64)
    if (tid < 64) {
        float* row = Qt + tid * 65;
        float mx = row[0];
        for (int p = 1; p < 64; p++) mx = fmaxf(mx, row[p]);
        float sum = 0.f;
        for (int p = 0; p < 64; p++) { float e = __expf(row[p] - mx); row[p] = e; sum += e; }
        float inv = 1.f / sum;
        for (int p = 0; p < 64; p++) row[p] *= inv;
    }
    __syncthreads();

    // O = P @ V
    float o[4][4];
#pragma unroll
    for (int i = 0; i < 4; i++)
#pragma unroll
        for (int j = 0; j < 4; j++) o[i][j] = 0.f;

    for (int p = 0; p < 64; ++p) {
        float a[4];
#pragma unroll
        for (int i = 0; i < 4; i++) a[i] = Qt[(ty * 4 + i) * 65 + p];
        float4 vv = *(const float4*)&Vs[p * 64 + tx * 4];
#pragma unroll
        for (int i = 0; i < 4; i++) {
            o[i][0] += a[i] * vv.x;
            o[i][1] += a[i] * vv.y;
            o[i][2] += a[i] * vv.z;
            o[i][3] += a[i] * vv.w;
        }
    }

#pragma unroll
    for (int i = 0; i < 4; i++) {
        float4 w = make_float4(o[i][0], o[i][1], o[i][2], o[i][3]);
        *(float4*)(O + base + (size_t)(ty * 4 + i) * rstride + tx * 4) = w;
    }
}

// ---------------- launch ----------------
extern "C" void kernel_launch(void* const* d_in, const int* in_sizes, int n_in,
                              void* d_out, int out_size)
{
    const float* X     = (const float*)d_in[0];
    const float* Wq    = (const float*)d_in[1];
    const float* bq    = (const float*)d_in[2];
    const float* gq    = (const float*)d_in[3];
    const float* betaq = (const float*)d_in[4];
    const float* mq    = (const float*)d_in[5];
    const float* vq    = (const float*)d_in[6];
    const float* Wk    = (const float*)d_in[7];
    const float* bk    = (const float*)d_in[8];
    const float* gk    = (const float*)d_in[9];
    const float* betak = (const float*)d_in[10];
    const float* mk    = (const float*)d_in[11];
    const float* vk    = (const float*)d_in[12];
    const float* Wv    = (const float*)d_in[13];
    const float* bv    = (const float*)d_in[14];
    const float* Wo    = (const float*)d_in[15];
    const float* bo    = (const float*)d_in[16];
    float* out = (float*)d_out;

    // resolve device-global scratch addresses (no allocation)
    float *p_q, *p_k, *p_v, *p_ao, *p_wq, *p_wk, *p_wv, *p_wo, *p_bq, *p_bk;
    cudaGetSymbolAddress((void**)&p_q,  g_q);
    cudaGetSymbolAddress((void**)&p_k,  g_k);
    cudaGetSymbolAddress((void**)&p_v,  g_v);
    cudaGetSymbolAddress((void**)&p_ao, g_ao);
    cudaGetSymbolAddress((void**)&p_wq, g_wq);
    cudaGetSymbolAddress((void**)&p_wk, g_wk);
    cudaGetSymbolAddress((void**)&p_wv, g_wv);
    cudaGetSymbolAddress((void**)&p_wo, g_wo);
    cudaGetSymbolAddress((void**)&p_bq, g_bq);
    cudaGetSymbolAddress((void**)&p_bk, g_bk);

    // 1) repack weights (fold BN scale, transpose to [k][n])
    repack_conv<<<(KSZ * DD * DD + 255) / 256, 256>>>(Wq, gq, vq, p_wq);
    repack_conv<<<(KSZ * DD * DD + 255) / 256, 256>>>(Wk, gk, vk, p_wk);
    fold_bias<<<2, 256>>>(bq, gq, betaq, mq, vq, p_bq);
    fold_bias<<<2, 256>>>(bk, gk, betak, mk, vk, p_bk);
    repack_lin<<<(DD * DD + 255) / 256, 256>>>(Wv, p_wv);
    repack_lin<<<(DD * DD + 255) / 256, 256>>>(Wo, p_wo);

    // 2) projections
    dim3 gg(DD / 128, MM / 128);
    gemm_conv<3><<<gg, 256>>>(X, p_wq, p_bq, p_q);
    gemm_conv<3><<<gg, 256>>>(X, p_wk, p_bk, p_k);
    gemm_conv<1><<<gg, 256>>>(X, p_wv, bv, p_v);

    // 3) attention (8192 heads)
    const int smem = (2 * 64 * 65 + 64 * 64) * (int)sizeof(float);   // 49664 B
    cudaFuncSetAttribute(attn_kernel, cudaFuncAttributeMaxDynamicSharedMemorySize, smem);
    attn_kernel<<<BB * NV * KH, 256, smem>>>(p_q, p_k, p_v, p_ao);

    // 4) output projection -> d_out
    gemm_conv<1><<<gg, 256>>>(p_ao, p_wo, bo, out);
}

// round 5
// speedup vs baseline: 2.7574x; 2.7574x over previous
#include <cuda_runtime.h>
#include <cstdint>
#include <cstddef>

// ---------------- problem constants ----------------
#define BB 8
#define TT 64
#define NV 128
#define DD 512
#define KH 8
#define DH 64
#define KSZ 3
#define MM (BB*TT*NV)          // 65536 tokens
#define EPSBN 1e-5f

// ---------------- device scratch ----------------
__device__ float g_q [(size_t)MM * DD];
__device__ float g_k [(size_t)MM * DD];
__device__ float g_v [(size_t)MM * DD];
__device__ float g_ao[(size_t)MM * DD];
__device__ float g_wq[(size_t)KSZ * DD * DD];   // [tap][n=out][k=in], BN-scale folded
__device__ float g_wk[(size_t)KSZ * DD * DD];
__device__ float g_bq[DD];
__device__ float g_bk[DD];

// ---------------- helpers ----------------
__device__ __forceinline__ uint32_t smem_u32(const void* p) {
    uint32_t a;
    asm("{ .reg .u64 t; cvta.to.shared.u64 t, %1; cvt.u32.u64 %0, t; }" : "=r"(a) : "l"(p));
    return a;
}
__device__ __forceinline__ uint32_t tf32r(float x) {
    uint32_t y;
    asm("cvt.rna.tf32.f32 %0, %1;" : "=r"(y) : "f"(x));
    return y;
}
#define CP_ASYNC16(s, g) \
    asm volatile("cp.async.cg.shared.global [%0], [%1], 16;" :: "r"(s), "l"(g) : "memory")
#define CP_COMMIT()  asm volatile("cp.async.commit_group;" ::: "memory")
#define CP_WAIT1()   asm volatile("cp.async.wait_group 1;" ::: "memory")
#define CP_WAIT0()   asm volatile("cp.async.wait_group 0;" ::: "memory")

// ---------------- weight repack: dst[tap][n][k] = W[(n*D+k)*KS+tap] * g[n]*rsqrt(v[n]+eps) ----------------
__global__ void repack_conv(const float* __restrict__ W, const float* __restrict__ g,
                            const float* __restrict__ var, float* __restrict__ dst)
{
    int idx = blockIdx.x * 256 + threadIdx.x;
    if (idx >= KSZ * DD * DD) return;
    int k   = idx & (DD - 1);
    int n   = (idx >> 9) & (DD - 1);
    int tap = idx >> 18;
    float scale = g[n] * rsqrtf(var[n] + EPSBN);
    dst[idx] = W[((size_t)n * DD + k) * KSZ + tap] * scale;
}

__global__ void fold_bias(const float* __restrict__ b, const float* __restrict__ g,
                          const float* __restrict__ beta, const float* __restrict__ m,
                          const float* __restrict__ v, float* __restrict__ dst)
{
    int o = blockIdx.x * 256 + threadIdx.x;
    if (o >= DD) return;
    float scale = g[o] * rsqrtf(v[o] + EPSBN);
    dst[o] = (b[o] - m[o]) * scale + beta[o];
}

// ---------------- TF32 mma.sync GEMM, fused causal conv taps ----------------
// C[128 rows @ tile bt][128 cols @ bn] = sum_taps sum_K A * B^T + bias
// A: activations [M, 512]; tap shift s = whole-tile row offset (bt - s); skip if t < s.
// B: weights [tap][n][k] row-major (k contiguous).
// smem tile layout: [stage][row][k] with row pitch 36 floats (conflict-free frag loads).
#define SPITCH 36
#define STG_FLOATS (128 * SPITCH)
#define GEMM_SMEM (4 * STG_FLOATS * 4)   // 2 stages x (A + B) = 73728 B

template<int TAPS>
__global__ void __launch_bounds__(256) gemm_mma(
    const float* __restrict__ A, const float* __restrict__ Bt,
    const float* __restrict__ bias, float* __restrict__ C)
{
    extern __shared__ float sm[];
    float* As = sm;                      // [2][128][36]
    float* Bs = sm + 2 * STG_FLOATS;     // [2][128][36]

    const int tid  = threadIdx.x;
    const int lane = tid & 31;
    const int wid  = tid >> 5;
    const int warpM = (wid & 3) * 32;    // 4 warps along M
    const int warpN = (wid >> 2) * 64;   // 2 warps along N
    const int r  = lane >> 2;            // group id 0..7
    const int cc = lane & 3;             // thread-in-group 0..3

    const int bn = blockIdx.x * 128;
    const int bt = blockIdx.y;
    const int t  = bt & (TT - 1);

    // valid taps: shift s = (2 - tap), whole-tile row offset
    const float* abase[TAPS];
    const float* bbase[TAPS];
    int nvalid = 0;
#pragma unroll
    for (int tap = 0; tap < TAPS; ++tap) {
        const int s = (TAPS == 3) ? (2 - tap) : 0;
        if (t >= s) {
            abase[nvalid] = A + ((size_t)(bt - s) * NV) * DD;
            bbase[nvalid] = Bt + (size_t)tap * DD * DD;
            nvalid++;
        }
    }
    const int NCH = nvalid * (DD / 32);

    const uint32_t sA = smem_u32(As);
    const uint32_t sB = smem_u32(Bs);

    float acc[2][8][4];
#pragma unroll
    for (int mt = 0; mt < 2; mt++)
#pragma unroll
        for (int nt = 0; nt < 8; nt++)
#pragma unroll
            for (int i = 0; i < 4; i++) acc[mt][nt][i] = 0.f;

    // ---- async tile load: chunk ci -> stage stg ----
    auto issue_load = [&](int ci, int stg) {
        const int ti = ci >> 4;
        const int kc = ci & 15;
        const float* ap = abase[ti] + kc * 32;
        const float* bp = bbase[ti] + (size_t)bn * DD + kc * 32;
        const uint32_t sbase = (uint32_t)(stg * STG_FLOATS) * 4u;
#pragma unroll
        for (int p = 0; p < 4; p++) {
            int idx = tid + 256 * p;
            int row = idx >> 3;
            int cv  = idx & 7;
            uint32_t so = sbase + (uint32_t)(row * SPITCH + cv * 4) * 4u;
            CP_ASYNC16(sA + so, ap + (size_t)row * DD + cv * 4);
            CP_ASYNC16(sB + so, bp + (size_t)row * DD + cv * 4);
        }
        CP_COMMIT();
    };

    // ---- compute one 32-K chunk from stage stg ----
    auto compute = [&](int stg) {
        const float* Ast = As + stg * STG_FLOATS;
        const float* Bst = Bs + stg * STG_FLOATS;
#pragma unroll
        for (int ks = 0; ks < 4; ks++) {
            uint32_t af[2][4], bf[8][2];
#pragma unroll
            for (int mt = 0; mt < 2; mt++) {
                const float* ap = Ast + (warpM + mt * 16 + r) * SPITCH + ks * 8 + cc;
                af[mt][0] = tf32r(ap[0]);
                af[mt][1] = tf32r(ap[8 * SPITCH]);
                af[mt][2] = tf32r(ap[4]);
                af[mt][3] = tf32r(ap[8 * SPITCH + 4]);
            }
#pragma unroll
            for (int nt = 0; nt < 8; nt++) {
                const float* bp = Bst + (warpN + nt * 8 + r) * SPITCH + ks * 8 + cc;
                bf[nt][0] = tf32r(bp[0]);
                bf[nt][1] = tf32r(bp[4]);
            }
#pragma unroll
            for (int mt = 0; mt < 2; mt++)
#pragma unroll
                for (int nt = 0; nt < 8; nt++)
                    asm volatile(
                        "mma.sync.aligned.m16n8k8.row.col.f32.tf32.tf32.f32 "
                        "{%0,%1,%2,%3}, {%4,%5,%6,%7}, {%8,%9}, {%0,%1,%2,%3};"
                        : "+f"(acc[mt][nt][0]), "+f"(acc[mt][nt][1]),
                          "+f"(acc[mt][nt][2]), "+f"(acc[mt][nt][3])
                        : "r"(af[mt][0]), "r"(af[mt][1]), "r"(af[mt][2]), "r"(af[mt][3]),
                          "r"(bf[nt][0]), "r"(bf[nt][1]));
        }
    };

    // ---- pipeline ----
    issue_load(0, 0);
    for (int ci = 0; ci < NCH; ci++) {
        const int stg = ci & 1;
        if (ci + 1 < NCH) { issue_load(ci + 1, stg ^ 1); CP_WAIT1(); }
        else              { CP_WAIT0(); }
        __syncthreads();
        compute(stg);
        __syncthreads();
    }

    // ---- epilogue: + bias, write fp32 ----
    const size_t m0 = (size_t)bt * NV;
#pragma unroll
    for (int mt = 0; mt < 2; mt++) {
        const int rw = warpM + mt * 16 + r;
#pragma unroll
        for (int nt = 0; nt < 8; nt++) {
            const int col = bn + warpN + nt * 8 + 2 * cc;
            const float bx = bias[col], by = bias[col + 1];
            float2 v0 = make_float2(acc[mt][nt][0] + bx, acc[mt][nt][1] + by);
            float2 v1 = make_float2(acc[mt][nt][2] + bx, acc[mt][nt][3] + by);
            *(float2*)(C + (m0 + rw)     * DD + col) = v0;
            *(float2*)(C + (m0 + rw + 8) * DD + col) = v1;
        }
    }
}

// ---------------- attention: one block per (b, n, h) head; T=64, DH=64 (fp32) ----------------
__global__ void __launch_bounds__(256) attn_kernel(
    const float* __restrict__ Q, const float* __restrict__ K,
    const float* __restrict__ V, float* __restrict__ O)
{
    extern __shared__ float sma[];
    float* Qt = sma;                 // pitch 65; reused as softmax matrix
    float* Kt = sma + 64 * 65;
    float* Vs = sma + 2 * 64 * 65;

    const int tid = threadIdx.x;
    const int hid = blockIdx.x;
    const int h = hid & 7;
    const int n = (hid >> 3) & 127;
    const int b = hid >> 10;
    const size_t base = (((size_t)b * TT) * NV + n) * DD + h * DH;
    const size_t rstride = (size_t)NV * DD;

    {
        int row = tid >> 2;
        int c0  = (tid & 3) * 16;
        const float* qr = Q + base + (size_t)row * rstride;
        const float* kr = K + base + (size_t)row * rstride;
        const float* vr = V + base + (size_t)row * rstride;
#pragma unroll
        for (int u = 0; u < 4; ++u) {
            int d0 = c0 + u * 4;
            float4 qv = *(const float4*)(qr + d0);
            float4 kv = *(const float4*)(kr + d0);
            float4 vv = *(const float4*)(vr + d0);
            Qt[(d0 + 0) * 65 + row] = qv.x;
            Qt[(d0 + 1) * 65 + row] = qv.y;
            Qt[(d0 + 2) * 65 + row] = qv.z;
            Qt[(d0 + 3) * 65 + row] = qv.w;
            Kt[(d0 + 0) * 65 + row] = kv.x;
            Kt[(d0 + 1) * 65 + row] = kv.y;
            Kt[(d0 + 2) * 65 + row] = kv.z;
            Kt[(d0 + 3) * 65 + row] = kv.w;
            *(float4*)&Vs[row * 64 + d0] = vv;
        }
    }
    __syncthreads();

    const int tx = tid & 15, ty = tid >> 4;

    float s[4][4];
#pragma unroll
    for (int i = 0; i < 4; i++)
#pragma unroll
        for (int j = 0; j < 4; j++) s[i][j] = 0.f;

    for (int kk = 0; kk < 64; ++kk) {
        float a[4], bb[4];
#pragma unroll
        for (int i = 0; i < 4; i++) a[i]  = Qt[kk * 65 + ty * 4 + i];
#pragma unroll
        for (int j = 0; j < 4; j++) bb[j] = Kt[kk * 65 + tx * 4 + j];
#pragma unroll
        for (int i = 0; i < 4; i++)
#pragma unroll
            for (int j = 0; j < 4; j++) s[i][j] += a[i] * bb[j];
    }
    __syncthreads();

#pragma unroll
    for (int i = 0; i < 4; i++)
#pragma unroll
        for (int j = 0; j < 4; j++)
            Qt[(ty * 4 + i) * 65 + tx * 4 + j] = s[i][j] * 0.125f;
    __syncthreads();

    if (tid < 64) {
        float* row = Qt + tid * 65;
        float mx = row[0];
        for (int p = 1; p < 64; p++) mx = fmaxf(mx, row[p]);
        float sum = 0.f;
        for (int p = 0; p < 64; p++) { float e = __expf(row[p] - mx); row[p] = e; sum += e; }
        float inv = 1.f / sum;
        for (int p = 0; p < 64; p++) row[p] *= inv;
    }
    __syncthreads();

    float o[4][4];
#pragma unroll
    for (int i = 0; i < 4; i++)
#pragma unroll
        for (int j = 0; j < 4; j++) o[i][j] = 0.f;

    for (int p = 0; p < 64; ++p) {
        float a[4];
#pragma unroll
        for (int i = 0; i < 4; i++) a[i] = Qt[(ty * 4 + i) * 65 + p];
        float4 vv = *(const float4*)&Vs[p * 64 + tx * 4];
#pragma unroll
        for (int i = 0; i < 4; i++) {
            o[i][0] += a[i] * vv.x;
            o[i][1] += a[i] * vv.y;
            o[i][2] += a[i] * vv.z;
            o[i][3] += a[i] * vv.w;
        }
    }

#pragma unroll
    for (int i = 0; i < 4; i++) {
        float4 w = make_float4(o[i][0], o[i][1], o[i][2], o[i][3]);
        *(float4*)(O + base + (size_t)(ty * 4 + i) * rstride + tx * 4) = w;
    }
}

// ---------------- launch ----------------
extern "C" void kernel_launch(void* const* d_in, const int* in_sizes, int n_in,
                              void* d_out, int out_size)
{
    const float* X     = (const float*)d_in[0];
    const float* Wq    = (const float*)d_in[1];
    const float* bq    = (const float*)d_in[2];
    const float* gq    = (const float*)d_in[3];
    const float* betaq = (const float*)d_in[4];
    const float* mq    = (const float*)d_in[5];
    const float* vq    = (const float*)d_in[6];
    const float* Wk    = (const float*)d_in[7];
    const float* bk    = (const float*)d_in[8];
    const float* gk    = (const float*)d_in[9];
    const float* betak = (const float*)d_in[10];
    const float* mk    = (const float*)d_in[11];
    const float* vk    = (const float*)d_in[12];
    const float* Wv    = (const float*)d_in[13];   // [out][in] = [n][k], used directly
    const float* bv    = (const float*)d_in[14];
    const float* Wo    = (const float*)d_in[15];
    const float* bo    = (const float*)d_in[16];
    float* out = (float*)d_out;

    float *p_q, *p_k, *p_v, *p_ao, *p_wq, *p_wk, *p_bq, *p_bk;
    cudaGetSymbolAddress((void**)&p_q,  g_q);
    cudaGetSymbolAddress((void**)&p_k,  g_k);
    cudaGetSymbolAddress((void**)&p_v,  g_v);
    cudaGetSymbolAddress((void**)&p_ao, g_ao);
    cudaGetSymbolAddress((void**)&p_wq, g_wq);
    cudaGetSymbolAddress((void**)&p_wk, g_wk);
    cudaGetSymbolAddress((void**)&p_bq, g_bq);
    cudaGetSymbolAddress((void**)&p_bk, g_bk);

    // 1) repack conv weights (fold BN scale, transpose to [tap][n][k]); fold biases
    repack_conv<<<(KSZ * DD * DD + 255) / 256, 256>>>(Wq, gq, vq, p_wq);
    repack_conv<<<(KSZ * DD * DD + 255) / 256, 256>>>(Wk, gk, vk, p_wk);
    fold_bias<<<2, 256>>>(bq, gq, betaq, mq, vq, p_bq);
    fold_bias<<<2, 256>>>(bk, gk, betak, mk, vk, p_bk);

    // 2) tensor-core TF32 projections (mma.sync, base-target ISA)
    cudaFuncSetAttribute(gemm_mma<3>, cudaFuncAttributeMaxDynamicSharedMemorySize, GEMM_SMEM);
    cudaFuncSetAttribute(gemm_mma<1>, cudaFuncAttributeMaxDynamicSharedMemorySize, GEMM_SMEM);
    dim3 gg(DD / 128, MM / NV);  // (4, 512)
    gemm_mma<3><<<gg, 256, GEMM_SMEM>>>(X, p_wq, p_bq, p_q);
    gemm_mma<3><<<gg, 256, GEMM_SMEM>>>(X, p_wk, p_bk, p_k);
    gemm_mma<1><<<gg, 256, GEMM_SMEM>>>(X, Wv, bv, p_v);

    // 3) attention (8192 heads)
    const int asmem = (2 * 64 * 65 + 64 * 64) * (int)sizeof(float);
    cudaFuncSetAttribute(attn_kernel, cudaFuncAttributeMaxDynamicSharedMemorySize, asmem);
    attn_kernel<<<BB * NV * KH, 256, asmem>>>(p_q, p_k, p_v, p_ao);

    // 4) output projection -> d_out
    gemm_mma<1><<<gg, 256, GEMM_SMEM>>>(p_ao, Wo, bo, out);
}

// round 7
// speedup vs baseline: 3.0359x; 1.1010x over previous
#include <cuda_runtime.h>
#include <cstdint>
#include <cstddef>

// ---------------- problem constants ----------------
#define BB 8
#define TT 64
#define NV 128
#define DD 512
#define KH 8
#define DH 64
#define KSZ 3
#define MM (BB*TT*NV)          // 65536 tokens
#define EPSBN 1e-5f

// ---------------- device scratch ----------------
__device__ float g_x [(size_t)MM * DD];          // tf32-rounded X
__device__ float g_q [(size_t)MM * DD];
__device__ float g_k [(size_t)MM * DD];
__device__ float g_v [(size_t)MM * DD];
__device__ float g_ao[(size_t)MM * DD];          // tf32-rounded attention out
__device__ float g_wqk[(size_t)KSZ * 1024 * DD]; // [tap][n:0..1023][k]; n<512 Wq, else Wk (BN folded, tf32)
__device__ float g_wv[(size_t)DD * DD];          // tf32-rounded [n][k]
__device__ float g_wo[(size_t)DD * DD];
__device__ float g_bqk[1024];

// ---------------- helpers ----------------
__device__ __forceinline__ uint32_t smem_u32(const void* p) {
    uint32_t a;
    asm("{ .reg .u64 t; cvta.to.shared.u64 t, %1; cvt.u32.u64 %0, t; }" : "=r"(a) : "l"(p));
    return a;
}
__device__ __forceinline__ float tf32rf(float x) {
    uint32_t y;
    asm("cvt.rna.tf32.f32 %0, %1;" : "=r"(y) : "f"(x));
    return __uint_as_float(y);
}
#define CP_ASYNC16(s, g) \
    asm volatile("cp.async.cg.shared.global [%0], [%1], 16;" :: "r"(s), "l"(g) : "memory")
#define CP_ASYNC16Z(s, g, sz) \
    asm volatile("cp.async.cg.shared.global [%0], [%1], 16, %2;" :: "r"(s), "l"(g), "r"(sz) : "memory")
#define CP_COMMIT()  asm volatile("cp.async.commit_group;" ::: "memory")
#define CP_WAIT1()   asm volatile("cp.async.wait_group 1;" ::: "memory")
#define CP_WAIT0()   asm volatile("cp.async.wait_group 0;" ::: "memory")

// ---------------- prep kernels ----------------
__global__ void round_x(const float* __restrict__ X, float* __restrict__ Y)
{
    size_t i = ((size_t)blockIdx.x * 256 + threadIdx.x) * 4;
    if (i >= (size_t)MM * DD) return;
    float4 v = *(const float4*)(X + i);
    v.x = tf32rf(v.x); v.y = tf32rf(v.y); v.z = tf32rf(v.z); v.w = tf32rf(v.w);
    *(float4*)(Y + i) = v;
}

// stacked conv weights: dst[tap][n'][k]; n'<512 from Wq, else Wk; BN scale folded; tf32-rounded
__global__ void repack_conv_qk(const float* __restrict__ Wq, const float* __restrict__ gq, const float* __restrict__ vq,
                               const float* __restrict__ Wk, const float* __restrict__ gk, const float* __restrict__ vk,
                               float* __restrict__ dst)
{
    int idx = blockIdx.x * 256 + threadIdx.x;
    if (idx >= KSZ * 1024 * DD) return;
    int k   = idx & (DD - 1);
    int np  = (idx >> 9) & 1023;
    int tap = idx >> 19;
    float w, scale;
    if (np < 512) {
        scale = gq[np] * rsqrtf(vq[np] + EPSBN);
        w = Wq[((size_t)np * DD + k) * KSZ + tap];
    } else {
        int n = np - 512;
        scale = gk[n] * rsqrtf(vk[n] + EPSBN);
        w = Wk[((size_t)n * DD + k) * KSZ + tap];
    }
    dst[idx] = tf32rf(w * scale);
}

__global__ void fold_bias_qk(const float* __restrict__ bq, const float* __restrict__ gq, const float* __restrict__ betaq,
                             const float* __restrict__ mq, const float* __restrict__ vq,
                             const float* __restrict__ bk, const float* __restrict__ gk, const float* __restrict__ betak,
                             const float* __restrict__ mk, const float* __restrict__ vk,
                             float* __restrict__ dst)
{
    int o = blockIdx.x * 256 + threadIdx.x;
    if (o >= 1024) return;
    if (o < 512) {
        float s = gq[o] * rsqrtf(vq[o] + EPSBN);
        dst[o] = (bq[o] - mq[o]) * s + betaq[o];
    } else {
        int n = o - 512;
        float s = gk[n] * rsqrtf(vk[n] + EPSBN);
        dst[o] = (bk[n] - mk[n]) * s + betak[n];
    }
}

__global__ void round_w(const float* __restrict__ W, float* __restrict__ dst)
{
    int i = blockIdx.x * 256 + threadIdx.x;
    if (i >= DD * DD) return;
    dst[i] = tf32rf(W[i]);
}

// ---------------- TF32 mma.sync GEMM: 256x128 tile, fused conv taps, stacked QK ----------------
// A: [M,512] tf32-rounded. B: [TAPS][NTOT][512] tf32-rounded, tap ti has shift s=2-ti (TAPS==3).
// M-tile = 256 rows (2 time steps); shift = whole-128-row offset; rows with t<s zero-filled.
#define MTILE 256
#define NTILE 128
#define APITCH 36
#define A_FLOATS (MTILE * APITCH)       // 9216
#define B_FLOATS (NTILE * APITCH)       // 4608
#define STGF (A_FLOATS + B_FLOATS)      // 13824 floats / stage
#define GEMM_SMEM (2 * STGF * 4)        // 110592 B

template<int TAPS>
__global__ void __launch_bounds__(256) gemm_mma(
    const float* __restrict__ A, const float* __restrict__ Bt,
    const float* __restrict__ bias, float* __restrict__ Cq, float* __restrict__ Ck)
{
    extern __shared__ float sm[];

    const int tid  = threadIdx.x;
    const int lane = tid & 31;
    const int wid  = tid >> 5;
    const int warpM = (wid & 3) * 64;     // 4 warps along M (256)
    const int warpN = (wid >> 2) * 64;    // 2 warps along N (128)
    const int r  = lane >> 2;
    const int cc = lane & 3;

    const int bnb = blockIdx.x;           // N-block in stacked space
    const int bty = blockIdx.y;           // 256-row M tile
    const size_t m0 = (size_t)bty * MTILE;

    const uint32_t sbase = smem_u32(sm);

    float acc[4][8][4];
#pragma unroll
    for (int mt = 0; mt < 4; mt++)
#pragma unroll
        for (int nt = 0; nt < 8; nt++)
#pragma unroll
            for (int i = 0; i < 4; i++) acc[mt][nt][i] = 0.f;

    const int NCH = TAPS * 16;

    auto issue_load = [&](int ci, int stg) {
        const int ti = ci >> 4;
        const int kc = ci & 15;
        const int s  = (TAPS == 3) ? (2 - ti) : 0;
        const float* ap = A + (m0 - (size_t)s * NV) * DD + kc * 32;
        const float* bp = Bt + (size_t)ti * 1024 * DD + ((size_t)bnb * NTILE) * DD + kc * 32;
        const uint32_t st = sbase + (uint32_t)(stg * STGF) * 4u;
        // A: 256 rows x 32 floats = 2048 quads, 8 per thread
#pragma unroll
        for (int p = 0; p < 8; p++) {
            int idx = tid + 256 * p;
            int row = idx >> 3;
            int cv  = idx & 7;
            uint32_t so = st + (uint32_t)(row * APITCH + cv * 4) * 4u;
            if (TAPS == 3) {
                int tloc = (int)((2 * bty + (row >> 7)) & 63);
                uint32_t sz = (tloc >= s) ? 16u : 0u;
                const float* src = (tloc >= s) ? (ap + (size_t)row * DD + cv * 4) : A;
                CP_ASYNC16Z(so, src, sz);
            } else {
                CP_ASYNC16(so, ap + (size_t)row * DD + cv * 4);
            }
        }
        // B: 128 rows x 32 floats = 1024 quads, 4 per thread
#pragma unroll
        for (int p = 0; p < 4; p++) {
            int idx = tid + 256 * p;
            int row = idx >> 3;
            int cv  = idx & 7;
            uint32_t so = st + (uint32_t)(A_FLOATS + row * APITCH + cv * 4) * 4u;
            CP_ASYNC16(so, bp + (size_t)row * DD + cv * 4);
        }
        CP_COMMIT();
    };

    auto compute = [&](int stg) {
        const float* Ast = sm + stg * STGF;
        const float* Bst = Ast + A_FLOATS;
#pragma unroll
        for (int ks = 0; ks < 4; ks++) {
            uint32_t af[4][4], bf[8][2];
#pragma unroll
            for (int mt = 0; mt < 4; mt++) {
                const float* ap = Ast + (warpM + mt * 16 + r) * APITCH + ks * 8 + cc;
                af[mt][0] = __float_as_uint(ap[0]);
                af[mt][1] = __float_as_uint(ap[8 * APITCH]);
                af[mt][2] = __float_as_uint(ap[4]);
                af[mt][3] = __float_as_uint(ap[8 * APITCH + 4]);
            }
#pragma unroll
            for (int nt = 0; nt < 8; nt++) {
                const float* bp = Bst + (warpN + nt * 8 + r) * APITCH + ks * 8 + cc;
                bf[nt][0] = __float_as_uint(bp[0]);
                bf[nt][1] = __float_as_uint(bp[4]);
            }
#pragma unroll
            for (int mt = 0; mt < 4; mt++)
#pragma unroll
                for (int nt = 0; nt < 8; nt++)
                    asm volatile(
                        "mma.sync.aligned.m16n8k8.row.col.f32.tf32.tf32.f32 "
                        "{%0,%1,%2,%3}, {%4,%5,%6,%7}, {%8,%9}, {%0,%1,%2,%3};"
                        : "+f"(acc[mt][nt][0]), "+f"(acc[mt][nt][1]),
                          "+f"(acc[mt][nt][2]), "+f"(acc[mt][nt][3])
                        : "r"(af[mt][0]), "r"(af[mt][1]), "r"(af[mt][2]), "r"(af[mt][3]),
                          "r"(bf[nt][0]), "r"(bf[nt][1]));
        }
    };

    issue_load(0, 0);
    for (int ci = 0; ci < NCH; ci++) {
        const int stg = ci & 1;
        if (ci + 1 < NCH) { issue_load(ci + 1, stg ^ 1); CP_WAIT1(); }
        else              { CP_WAIT0(); }
        __syncthreads();
        compute(stg);
        __syncthreads();
    }

    // epilogue: route stacked columns to Cq / Ck, add bias
    float* C;
    int cb;
    if (TAPS == 3 && bnb >= 4) { C = Ck; cb = bnb * NTILE - 512; }
    else                       { C = Cq; cb = bnb * NTILE; }
    const float* bp = bias + bnb * NTILE;

#pragma unroll
    for (int mt = 0; mt < 4; mt++) {
        const size_t rw = m0 + warpM + mt * 16 + r;
#pragma unroll
        for (int nt = 0; nt < 8; nt++) {
            const int cl = warpN + nt * 8 + 2 * cc;
            const float bx = bp[cl], by = bp[cl + 1];
            float2 v0 = make_float2(acc[mt][nt][0] + bx, acc[mt][nt][1] + by);
            float2 v1 = make_float2(acc[mt][nt][2] + bx, acc[mt][nt][3] + by);
            *(float2*)(C + rw       * DD + cb + cl) = v0;
            *(float2*)(C + (rw + 8) * DD + cb + cl) = v1;
        }
    }
}

// ---------------- attention: one block per (b, n, h) head; T=64, DH=64 (fp32) ----------------
__global__ void __launch_bounds__(256) attn_kernel(
    const float* __restrict__ Q, const float* __restrict__ K,
    const float* __restrict__ V, float* __restrict__ O)
{
    extern __shared__ float sma[];
    float* Qt = sma;                 // pitch 65; reused as softmax matrix
    float* Kt = sma + 64 * 65;
    float* Vs = sma + 2 * 64 * 65;

    const int tid = threadIdx.x;
    const int hid = blockIdx.x;
    const int h = hid & 7;
    const int n = (hid >> 3) & 127;
    const int b = hid >> 10;
    const size_t base = (((size_t)b * TT) * NV + n) * DD + h * DH;
    const size_t rstride = (size_t)NV * DD;

    {
        int row = tid >> 2;
        int c0  = (tid & 3) * 16;
        const float* qr = Q + base + (size_t)row * rstride;
        const float* kr = K + base + (size_t)row * rstride;
        const float* vr = V + base + (size_t)row * rstride;
#pragma unroll
        for (int u = 0; u < 4; ++u) {
            int d0 = c0 + u * 4;
            float4 qv = *(const float4*)(qr + d0);
            float4 kv = *(const float4*)(kr + d0);
            float4 vv = *(const float4*)(vr + d0);
            Qt[(d0 + 0) * 65 + row] = qv.x;
            Qt[(d0 + 1) * 65 + row] = qv.y;
            Qt[(d0 + 2) * 65 + row] = qv.z;
            Qt[(d0 + 3) * 65 + row] = qv.w;
            Kt[(d0 + 0) * 65 + row] = kv.x;
            Kt[(d0 + 1) * 65 + row] = kv.y;
            Kt[(d0 + 2) * 65 + row] = kv.z;
            Kt[(d0 + 3) * 65 + row] = kv.w;
            *(float4*)&Vs[row * 64 + d0] = vv;
        }
    }
    __syncthreads();

    const int tx = tid & 15, ty = tid >> 4;

    float s[4][4];
#pragma unroll
    for (int i = 0; i < 4; i++)
#pragma unroll
        for (int j = 0; j < 4; j++) s[i][j] = 0.f;

    for (int kk = 0; kk < 64; ++kk) {
        float a[4], bb[4];
#pragma unroll
        for (int i = 0; i < 4; i++) a[i]  = Qt[kk * 65 + ty * 4 + i];
#pragma unroll
        for (int j = 0; j < 4; j++) bb[j] = Kt[kk * 65 + tx * 4 + j];
#pragma unroll
        for (int i = 0; i < 4; i++)
#pragma unroll
            for (int j = 0; j < 4; j++) s[i][j] += a[i] * bb[j];
    }
    __syncthreads();

#pragma unroll
    for (int i = 0; i < 4; i++)
#pragma unroll
        for (int j = 0; j < 4; j++)
            Qt[(ty * 4 + i) * 65 + tx * 4 + j] = s[i][j] * 0.125f;
    __syncthreads();

    if (tid < 64) {
        float* row = Qt + tid * 65;
        float mx = row[0];
        for (int p = 1; p < 64; p++) mx = fmaxf(mx, row[p]);
        float sum = 0.f;
        for (int p = 0; p < 64; p++) { float e = __expf(row[p] - mx); row[p] = e; sum += e; }
        float inv = 1.f / sum;
        for (int p = 0; p < 64; p++) row[p] *= inv;
    }
    __syncthreads();

    float o[4][4];
#pragma unroll
    for (int i = 0; i < 4; i++)
#pragma unroll
        for (int j = 0; j < 4; j++) o[i][j] = 0.f;

    for (int p = 0; p < 64; ++p) {
        float a[4];
#pragma unroll
        for (int i = 0; i < 4; i++) a[i] = Qt[(ty * 4 + i) * 65 + p];
        float4 vv = *(const float4*)&Vs[p * 64 + tx * 4];
#pragma unroll
        for (int i = 0; i < 4; i++) {
            o[i][0] += a[i] * vv.x;
            o[i][1] += a[i] * vv.y;
            o[i][2] += a[i] * vv.z;
            o[i][3] += a[i] * vv.w;
        }
    }

    // store tf32-rounded (feeds O-projection MMA directly)
#pragma unroll
    for (int i = 0; i < 4; i++) {
        float4 w = make_float4(tf32rf(o[i][0]), tf32rf(o[i][1]),
                               tf32rf(o[i][2]), tf32rf(o[i][3]));
        *(float4*)(O + base + (size_t)(ty * 4 + i) * rstride + tx * 4) = w;
    }
}

// ---------------- launch ----------------
extern "C" void kernel_launch(void* const* d_in, const int* in_sizes, int n_in,
                              void* d_out, int out_size)
{
    const float* X     = (const float*)d_in[0];
    const float* Wq    = (const float*)d_in[1];
    const float* bq    = (const float*)d_in[2];
    const float* gq    = (const float*)d_in[3];
    const float* betaq = (const float*)d_in[4];
    const float* mq    = (const float*)d_in[5];
    const float* vq    = (const float*)d_in[6];
    const float* Wk    = (const float*)d_in[7];
    const float* bk    = (const float*)d_in[8];
    const float* gk    = (const float*)d_in[9];
    const float* betak = (const float*)d_in[10];
    const float* mk    = (const float*)d_in[11];
    const float* vk    = (const float*)d_in[12];
    const float* Wv    = (const float*)d_in[13];
    const float* bv    = (const float*)d_in[14];
    const float* Wo    = (const float*)d_in[15];
    const float* bo    = (const float*)d_in[16];
    float* out = (float*)d_out;

    float *p_x, *p_q, *p_k, *p_v, *p_ao, *p_wqk, *p_wv, *p_wo, *p_bqk;
    cudaGetSymbolAddress((void**)&p_x,   g_x);
    cudaGetSymbolAddress((void**)&p_q,   g_q);
    cudaGetSymbolAddress((void**)&p_k,   g_k);
    cudaGetSymbolAddress((void**)&p_v,   g_v);
    cudaGetSymbolAddress((void**)&p_ao,  g_ao);
    cudaGetSymbolAddress((void**)&p_wqk, g_wqk);
    cudaGetSymbolAddress((void**)&p_wv,  g_wv);
    cudaGetSymbolAddress((void**)&p_wo,  g_wo);
    cudaGetSymbolAddress((void**)&p_bqk, g_bqk);

    // 1) pre-round operands (removes all cvt from GEMM inner loops)
    round_x<<<(MM * DD / 4 + 255) / 256, 256>>>(X, p_x);
    repack_conv_qk<<<(KSZ * 1024 * DD + 255) / 256, 256>>>(Wq, gq, vq, Wk, gk, vk, p_wqk);
    fold_bias_qk<<<4, 256>>>(bq, gq, betaq, mq, vq, bk, gk, betak, mk, vk, p_bqk);
    round_w<<<(DD * DD + 255) / 256, 256>>>(Wv, p_wv);
    round_w<<<(DD * DD + 255) / 256, 256>>>(Wo, p_wo);

    // 2) projections (tensor cores, 256x128 tiles)
    cudaFuncSetAttribute(gemm_mma<3>, cudaFuncAttributeMaxDynamicSharedMemorySize, GEMM_SMEM);
    cudaFuncSetAttribute(gemm_mma<1>, cudaFuncAttributeMaxDynamicSharedMemorySize, GEMM_SMEM);
    dim3 gqk(1024 / NTILE, MM / MTILE);   // (8, 256) — fused Q+K
    dim3 gl (DD / NTILE,   MM / MTILE);   // (4, 256)
    gemm_mma<3><<<gqk, 256, GEMM_SMEM>>>(p_x, p_wqk, p_bqk, p_q, p_k);
    gemm_mma<1><<<gl,  256, GEMM_SMEM>>>(p_x, p_wv, bv, p_v, nullptr);

    // 3) attention (8192 heads), stores tf32-rounded output
    const int asmem = (2 * 64 * 65 + 64 * 64) * (int)sizeof(float);
    cudaFuncSetAttribute(attn_kernel, cudaFuncAttributeMaxDynamicSharedMemorySize, asmem);
    attn_kernel<<<BB * NV * KH, 256, asmem>>>(p_q, p_k, p_v, p_ao);

    // 4) output projection -> d_out
    gemm_mma<1><<<gl, 256, GEMM_SMEM>>>(p_ao, p_wo, bo, out, nullptr);
}

// round 9
// speedup vs baseline: 4.5002x; 1.4823x over previous
#include <cuda_runtime.h>
#include <cuda_fp16.h>
#include <cstdint>
#include <cstddef>

// ---------------- problem constants ----------------
#define BB 8
#define TT 64
#define NV 128
#define DD 512
#define KH 8
#define DH 64
#define KSZ 3
#define MM (BB*TT*NV)          // 65536 tokens
#define EPSBN 1e-5f

// ---------------- device scratch ----------------
__device__ __half g_xh[(size_t)MM * DD];          // fp16 X
__device__ float  g_q [(size_t)MM * DD];
__device__ float  g_k [(size_t)MM * DD];
__device__ float  g_v [(size_t)MM * DD];
__device__ __half g_ao[(size_t)MM * DD];          // fp16 attention out
__device__ __half g_wqk[(size_t)KSZ * 1024 * DD]; // [tap][n'][k]; n'<512 Wq else Wk (BN folded)
__device__ __half g_wv[(size_t)DD * DD];          // [n][k]
__device__ __half g_wo[(size_t)DD * DD];
__device__ float  g_bqk[1024];

// ---------------- helpers ----------------
__device__ __forceinline__ uint32_t smem_u32(const void* p) {
    uint32_t a;
    asm("{ .reg .u64 t; cvta.to.shared.u64 t, %1; cvt.u32.u64 %0, t; }" : "=r"(a) : "l"(p));
    return a;
}
#define CP_ASYNC16(s, g) \
    asm volatile("cp.async.cg.shared.global [%0], [%1], 16;" :: "r"(s), "l"(g) : "memory")
#define CP_ASYNC16Z(s, g, sz) \
    asm volatile("cp.async.cg.shared.global [%0], [%1], 16, %2;" :: "r"(s), "l"(g), "r"(sz) : "memory")
#define CP_COMMIT()  asm volatile("cp.async.commit_group;" ::: "memory")
#define CP_WAIT1()   asm volatile("cp.async.wait_group 1;" ::: "memory")
#define CP_WAIT0()   asm volatile("cp.async.wait_group 0;" ::: "memory")
#define LDMX4(r0, r1, r2, r3, a) \
    asm volatile("ldmatrix.sync.aligned.m8n8.x4.shared.b16 {%0,%1,%2,%3}, [%4];" \
        : "=r"(r0), "=r"(r1), "=r"(r2), "=r"(r3) : "r"(a))
#define MMA16816(c, a, b) \
    asm volatile("mma.sync.aligned.m16n8k16.row.col.f32.f16.f16.f32 " \
        "{%0,%1,%2,%3}, {%4,%5,%6,%7}, {%8,%9}, {%0,%1,%2,%3};" \
        : "+f"((c)[0]), "+f"((c)[1]), "+f"((c)[2]), "+f"((c)[3]) \
        : "r"((a)[0]), "r"((a)[1]), "r"((a)[2]), "r"((a)[3]), "r"((b)[0]), "r"((b)[1]))

// ---------------- prep kernels ----------------
__global__ void x_to_half(const float* __restrict__ X, __half* __restrict__ Y)
{
    size_t i = ((size_t)blockIdx.x * 256 + threadIdx.x) * 8;
    if (i >= (size_t)MM * DD) return;
    float4 v0 = *(const float4*)(X + i);
    float4 v1 = *(const float4*)(X + i + 4);
    __half2 h0 = __floats2half2_rn(v0.x, v0.y);
    __half2 h1 = __floats2half2_rn(v0.z, v0.w);
    __half2 h2 = __floats2half2_rn(v1.x, v1.y);
    __half2 h3 = __floats2half2_rn(v1.z, v1.w);
    uint4 o = make_uint4(*(uint32_t*)&h0, *(uint32_t*)&h1, *(uint32_t*)&h2, *(uint32_t*)&h3);
    *(uint4*)(Y + i) = o;
}

__global__ void repack_conv_qk(const float* __restrict__ Wq, const float* __restrict__ gq, const float* __restrict__ vq,
                               const float* __restrict__ Wk, const float* __restrict__ gk, const float* __restrict__ vk,
                               __half* __restrict__ dst)
{
    int idx = blockIdx.x * 256 + threadIdx.x;
    if (idx >= KSZ * 1024 * DD) return;
    int k   = idx & (DD - 1);
    int np  = (idx >> 9) & 1023;
    int tap = idx >> 19;
    float w, scale;
    if (np < 512) {
        scale = gq[np] * rsqrtf(vq[np] + EPSBN);
        w = Wq[((size_t)np * DD + k) * KSZ + tap];
    } else {
        int n = np - 512;
        scale = gk[n] * rsqrtf(vk[n] + EPSBN);
        w = Wk[((size_t)n * DD + k) * KSZ + tap];
    }
    dst[idx] = __float2half_rn(w * scale);
}

__global__ void fold_bias_qk(const float* __restrict__ bq, const float* __restrict__ gq, const float* __restrict__ betaq,
                             const float* __restrict__ mq, const float* __restrict__ vq,
                             const float* __restrict__ bk, const float* __restrict__ gk, const float* __restrict__ betak,
                             const float* __restrict__ mk, const float* __restrict__ vk,
                             float* __restrict__ dst)
{
    int o = blockIdx.x * 256 + threadIdx.x;
    if (o >= 1024) return;
    if (o < 512) {
        float s = gq[o] * rsqrtf(vq[o] + EPSBN);
        dst[o] = (bq[o] - mq[o]) * s + betaq[o];
    } else {
        int n = o - 512;
        float s = gk[n] * rsqrtf(vk[n] + EPSBN);
        dst[o] = (bk[n] - mk[n]) * s + betak[n];
    }
}

__global__ void w_to_half(const float* __restrict__ Wv, const float* __restrict__ Wo,
                          __half* __restrict__ dv, __half* __restrict__ dw)
{
    int i = blockIdx.x * 256 + threadIdx.x;
    if (i < DD * DD) dv[i] = __float2half_rn(Wv[i]);
    else if (i < 2 * DD * DD) dw[i - DD * DD] = __float2half_rn(Wo[i - DD * DD]);
}

// ---------------- fp16 mma.sync GEMM: 256x128 tile, fused conv taps, stacked QK ----------------
// A: [M,512] fp16. B: [TAPS][NTOT][512] fp16 (n-major, k contiguous); tap ti shift s=2-ti.
// M-tile = 256 rows (2 time steps); shift = whole-128-row offset; rows with t<s zero-filled.
#define MTILE 256
#define NTILE 128
#define KCH 32
#define HPITCH 40                       // halves per row (80 B, conflict-free ldmatrix)
#define A_BYTES (MTILE * HPITCH * 2)    // 20480
#define B_BYTES (NTILE * HPITCH * 2)    // 10240
#define STG_BYTES (A_BYTES + B_BYTES)   // 30720
#define NSTAGE 3
#define GEMM_SMEM (NSTAGE * STG_BYTES)  // 92160

template<int TAPS>
__global__ void __launch_bounds__(256) gemm_h(
    const __half* __restrict__ A, const __half* __restrict__ Bt,
    const float* __restrict__ bias, float* __restrict__ Cq, float* __restrict__ Ck)
{
    extern __shared__ char smc[];

    const int tid  = threadIdx.x;
    const int lane = tid & 31;
    const int wid  = tid >> 5;
    const int warpM = (wid & 3) * 64;     // 4 warps along M (256)
    const int warpN = (wid >> 2) * 64;    // 2 warps along N (128)
    const int r4  = lane >> 2;            // 0..7
    const int c2  = lane & 3;             // 0..3
    const int mat = lane >> 3;            // 0..3 (ldmatrix phase)
    const int r8  = lane & 7;

    const int bnb = blockIdx.x;
    const int bty = blockIdx.y;
    const size_t m0 = (size_t)bty * MTILE;

    const uint32_t sbase = smem_u32(smc);

    // ldmatrix lane-relative byte offsets (stage-relative)
    // A tile (mt, ks): row = warpM + mt*16 + (mat&1)*8 + r8 ; colh = ks*16 + (mat>>1)*8
    const uint32_t aoff0 = (uint32_t)(((warpM + ((mat & 1) << 3) + r8) * HPITCH + ((mat >> 1) << 3)) * 2);
    // B pair (np, ks): n = warpN + np*16 + (mat>>1)*8 + r8 ; colh = ks*16 + (mat&1)*8
    const uint32_t boff0 = (uint32_t)(A_BYTES + ((warpN + ((mat >> 1) << 3) + r8) * HPITCH + ((mat & 1) << 3)) * 2);

    float acc[4][8][4];
#pragma unroll
    for (int mt = 0; mt < 4; mt++)
#pragma unroll
        for (int nt = 0; nt < 8; nt++)
#pragma unroll
            for (int i = 0; i < 4; i++) acc[mt][nt][i] = 0.f;

    const int NCH = TAPS * (DD / KCH);

    auto issue_load = [&](int ci, int stg) {
        const int ti = ci >> 4;
        const int kc = ci & 15;
        const int s  = (TAPS == 3) ? (2 - ti) : 0;
        const __half* ap = A + (m0 - (size_t)s * NV) * DD + kc * KCH;
        const __half* bp = Bt + ((TAPS == 3) ? (size_t)ti * 1024 * DD : 0)
                               + ((size_t)bnb * NTILE) * DD + kc * KCH;
        const uint32_t st = sbase + (uint32_t)stg * STG_BYTES;
        // A: 256 rows x 32 halves = 1024 x 16B
#pragma unroll
        for (int p = 0; p < 4; p++) {
            int idx = tid + 256 * p;
            int row = idx >> 2;
            int q   = idx & 3;
            uint32_t so = st + (uint32_t)(row * HPITCH + q * 8) * 2u;
            if (TAPS == 3) {
                int tloc = (int)((2 * bty + (row >> 7)) & 63);
                uint32_t sz = (tloc >= s) ? 16u : 0u;
                const __half* src = (tloc >= s) ? (ap + (size_t)row * DD + q * 8) : A;
                CP_ASYNC16Z(so, src, sz);
            } else {
                CP_ASYNC16(so, ap + (size_t)row * DD + q * 8);
            }
        }
        // B: 128 rows x 32 halves = 512 x 16B
#pragma unroll
        for (int p = 0; p < 2; p++) {
            int idx = tid + 256 * p;
            int row = idx >> 2;
            int q   = idx & 3;
            uint32_t so = st + (uint32_t)A_BYTES + (uint32_t)(row * HPITCH + q * 8) * 2u;
            CP_ASYNC16(so, bp + (size_t)row * DD + q * 8);
        }
        CP_COMMIT();
    };

    auto compute = [&](int stg) {
        const uint32_t st = sbase + (uint32_t)stg * STG_BYTES;
        const uint32_t abase = st + aoff0;
        const uint32_t bbase = st + boff0;
#pragma unroll
        for (int ks = 0; ks < 2; ks++) {
            uint32_t af[4][4], bf[8][2];
#pragma unroll
            for (int mt = 0; mt < 4; mt++)
                LDMX4(af[mt][0], af[mt][1], af[mt][2], af[mt][3],
                      abase + (uint32_t)((mt * 16 * HPITCH + ks * 16) * 2));
#pragma unroll
            for (int np = 0; np < 4; np++)
                LDMX4(bf[2*np][0], bf[2*np][1], bf[2*np+1][0], bf[2*np+1][1],
                      bbase + (uint32_t)((np * 16 * HPITCH + ks * 16) * 2));
#pragma unroll
            for (int mt = 0; mt < 4; mt++)
#pragma unroll
                for (int nt = 0; nt < 8; nt++)
                    MMA16816(acc[mt][nt], af[mt], bf[nt]);
        }
    };

    // ---- 3-stage pipeline ----
    issue_load(0, 0);
    issue_load(1, 1);
    for (int ci = 0; ci < NCH; ci++) {
        if (ci + 1 < NCH) CP_WAIT1(); else CP_WAIT0();
        __syncthreads();
        compute(ci % NSTAGE);
        __syncthreads();
        if (ci + 2 < NCH) issue_load(ci + 2, (ci + 2) % NSTAGE);
    }

    // ---- epilogue: route stacked columns to Cq / Ck, add bias ----
    float* C;
    int cb;
    if (TAPS == 3 && bnb >= 4) { C = Ck; cb = bnb * NTILE - 512; }
    else                       { C = Cq; cb = bnb * NTILE; }
    const float* bp = bias + bnb * NTILE;

#pragma unroll
    for (int mt = 0; mt < 4; mt++) {
        const size_t rw = m0 + warpM + mt * 16 + r4;
#pragma unroll
        for (int nt = 0; nt < 8; nt++) {
            const int cl = warpN + nt * 8 + 2 * c2;
            const float bx = bp[cl], by = bp[cl + 1];
            float2 v0 = make_float2(acc[mt][nt][0] + bx, acc[mt][nt][1] + by);
            float2 v1 = make_float2(acc[mt][nt][2] + bx, acc[mt][nt][3] + by);
            *(float2*)(C + rw       * DD + cb + cl) = v0;
            *(float2*)(C + (rw + 8) * DD + cb + cl) = v1;
        }
    }
}

// ---------------- attention: one block per (b, n, h) head; T=64, DH=64 (fp32 in, fp16 out) ----------------
__global__ void __launch_bounds__(256) attn_kernel(
    const float* __restrict__ Q, const float* __restrict__ K,
    const float* __restrict__ V, __half* __restrict__ O)
{
    extern __shared__ float sma[];
    float* Qt = sma;                 // pitch 65; reused as softmax matrix
    float* Kt = sma + 64 * 65;
    float* Vs = sma + 2 * 64 * 65;

    const int tid = threadIdx.x;
    const int hid = blockIdx.x;
    const int h = hid & 7;
    const int n = (hid >> 3) & 127;
    const int b = hid >> 10;
    const size_t base = (((size_t)b * TT) * NV + n) * DD + h * DH;
    const size_t rstride = (size_t)NV * DD;

    {
        int row = tid >> 2;
        int c0  = (tid & 3) * 16;
        const float* qr = Q + base + (size_t)row * rstride;
        const float* kr = K + base + (size_t)row * rstride;
        const float* vr = V + base + (size_t)row * rstride;
#pragma unroll
        for (int u = 0; u < 4; ++u) {
            int d0 = c0 + u * 4;
            float4 qv = *(const float4*)(qr + d0);
            float4 kv = *(const float4*)(kr + d0);
            float4 vv = *(const float4*)(vr + d0);
            Qt[(d0 + 0) * 65 + row] = qv.x;
            Qt[(d0 + 1) * 65 + row] = qv.y;
            Qt[(d0 + 2) * 65 + row] = qv.z;
            Qt[(d0 + 3) * 65 + row] = qv.w;
            Kt[(d0 + 0) * 65 + row] = kv.x;
            Kt[(d0 + 1) * 65 + row] = kv.y;
            Kt[(d0 + 2) * 65 + row] = kv.z;
            Kt[(d0 + 3) * 65 + row] = kv.w;
            *(float4*)&Vs[row * 64 + d0] = vv;
        }
    }
    __syncthreads();

    const int tx = tid & 15, ty = tid >> 4;

    float s[4][4];
#pragma unroll
    for (int i = 0; i < 4; i++)
#pragma unroll
        for (int j = 0; j < 4; j++) s[i][j] = 0.f;

    for (int kk = 0; kk < 64; ++kk) {
        float a[4], bb[4];
#pragma unroll
        for (int i = 0; i < 4; i++) a[i]  = Qt[kk * 65 + ty * 4 + i];
#pragma unroll
        for (int j = 0; j < 4; j++) bb[j] = Kt[kk * 65 + tx * 4 + j];
#pragma unroll
        for (int i = 0; i < 4; i++)
#pragma unroll
            for (int j = 0; j < 4; j++) s[i][j] += a[i] * bb[j];
    }
    __syncthreads();

#pragma unroll
    for (int i = 0; i < 4; i++)
#pragma unroll
        for (int j = 0; j < 4; j++)
            Qt[(ty * 4 + i) * 65 + tx * 4 + j] = s[i][j] * 0.125f;
    __syncthreads();

    if (tid < 64) {
        float* row = Qt + tid * 65;
        float mx = row[0];
        for (int p = 1; p < 64; p++) mx = fmaxf(mx, row[p]);
        float sum = 0.f;
        for (int p = 0; p < 64; p++) { float e = __expf(row[p] - mx); row[p] = e; sum += e; }
        float inv = 1.f / sum;
        for (int p = 0; p < 64; p++) row[p] *= inv;
    }
    __syncthreads();

    float o[4][4];
#pragma unroll
    for (int i = 0; i < 4; i++)
#pragma unroll
        for (int j = 0; j < 4; j++) o[i][j] = 0.f;

    for (int p = 0; p < 64; ++p) {
        float a[4];
#pragma unroll
        for (int i = 0; i < 4; i++) a[i] = Qt[(ty * 4 + i) * 65 + p];
        float4 vv = *(const float4*)&Vs[p * 64 + tx * 4];
#pragma unroll
        for (int i = 0; i < 4; i++) {
            o[i][0] += a[i] * vv.x;
            o[i][1] += a[i] * vv.y;
            o[i][2] += a[i] * vv.z;
            o[i][3] += a[i] * vv.w;
        }
    }

    // store fp16 (feeds O-projection MMA directly)
#pragma unroll
    for (int i = 0; i < 4; i++) {
        __half2 h01 = __floats2half2_rn(o[i][0], o[i][1]);
        __half2 h23 = __floats2half2_rn(o[i][2], o[i][3]);
        uint2 w = make_uint2(*(uint32_t*)&h01, *(uint32_t*)&h23);
        *(uint2*)(O + base + (size_t)(ty * 4 + i) * rstride + tx * 4) = w;
    }
}

// ---------------- launch ----------------
extern "C" void kernel_launch(void* const* d_in, const int* in_sizes, int n_in,
                              void* d_out, int out_size)
{
    const float* X     = (const float*)d_in[0];
    const float* Wq    = (const float*)d_in[1];
    const float* bq    = (const float*)d_in[2];
    const float* gq    = (const float*)d_in[3];
    const float* betaq = (const float*)d_in[4];
    const float* mq    = (const float*)d_in[5];
    const float* vq    = (const float*)d_in[6];
    const float* Wk    = (const float*)d_in[7];
    const float* bk    = (const float*)d_in[8];
    const float* gk    = (const float*)d_in[9];
    const float* betak = (const float*)d_in[10];
    const float* mk    = (const float*)d_in[11];
    const float* vk    = (const float*)d_in[12];
    const float* Wv    = (const float*)d_in[13];
    const float* bv    = (const float*)d_in[14];
    const float* Wo    = (const float*)d_in[15];
    const float* bo    = (const float*)d_in[16];
    float* out = (float*)d_out;

    __half *p_xh, *p_ao, *p_wqk, *p_wv, *p_wo;
    float *p_q, *p_k, *p_v, *p_bqk;
    cudaGetSymbolAddress((void**)&p_xh,  g_xh);
    cudaGetSymbolAddress((void**)&p_q,   g_q);
    cudaGetSymbolAddress((void**)&p_k,   g_k);
    cudaGetSymbolAddress((void**)&p_v,   g_v);
    cudaGetSymbolAddress((void**)&p_ao,  g_ao);
    cudaGetSymbolAddress((void**)&p_wqk, g_wqk);
    cudaGetSymbolAddress((void**)&p_wv,  g_wv);
    cudaGetSymbolAddress((void**)&p_wo,  g_wo);
    cudaGetSymbolAddress((void**)&p_bqk, g_bqk);

    // 1) fp16 operand prep
    x_to_half<<<(MM * DD / 8 + 255) / 256, 256>>>(X, p_xh);
    repack_conv_qk<<<(KSZ * 1024 * DD + 255) / 256, 256>>>(Wq, gq, vq, Wk, gk, vk, p_wqk);
    fold_bias_qk<<<4, 256>>>(bq, gq, betaq, mq, vq, bk, gk, betak, mk, vk, p_bqk);
    w_to_half<<<(2 * DD * DD + 255) / 256, 256>>>(Wv, Wo, p_wv, p_wo);

    // 2) projections (fp16 tensor cores, 256x128 tiles)
    cudaFuncSetAttribute(gemm_h<3>, cudaFuncAttributeMaxDynamicSharedMemorySize, GEMM_SMEM);
    cudaFuncSetAttribute(gemm_h<1>, cudaFuncAttributeMaxDynamicSharedMemorySize, GEMM_SMEM);
    dim3 gqk(1024 / NTILE, MM / MTILE);   // (8, 256) — fused Q+K
    dim3 gl (DD / NTILE,   MM / MTILE);   // (4, 256)
    gemm_h<3><<<gqk, 256, GEMM_SMEM>>>(p_xh, p_wqk, p_bqk, p_q, p_k);
    gemm_h<1><<<gl,  256, GEMM_SMEM>>>(p_xh, p_wv, bv, p_v, nullptr);

    // 3) attention (8192 heads), writes fp16
    const int asmem = (2 * 64 * 65 + 64 * 64) * (int)sizeof(float);
    cudaFuncSetAttribute(attn_kernel, cudaFuncAttributeMaxDynamicSharedMemorySize, asmem);
    attn_kernel<<<BB * NV * KH, 256, asmem>>>(p_q, p_k, p_v, p_ao);

    // 4) output projection -> d_out
    gemm_h<1><<<gl, 256, GEMM_SMEM>>>(p_ao, p_wo, bo, out, nullptr);
}

// round 11
// speedup vs baseline: 5.4190x; 1.2042x over previous
#include <cuda_runtime.h>
#include <cuda_fp16.h>
#include <cstdint>
#include <cstddef>

// ---------------- problem constants ----------------
#define BB 8
#define TT 64
#define NV 128
#define DD 512
#define KH 8
#define DH 64
#define KSZ 3
#define MM (BB*TT*NV)          // 65536 tokens
#define EPSBN 1e-5f

// ---------------- device scratch ----------------
__device__ __half g_xh[(size_t)MM * DD];          // fp16 X
__device__ __half g_qh[(size_t)MM * DD];          // fp16 Q
__device__ __half g_kh[(size_t)MM * DD];          // fp16 K
__device__ __half g_vh[(size_t)MM * DD];          // fp16 V
__device__ __half g_ao[(size_t)MM * DD];          // fp16 attention out
__device__ __half g_wqk[(size_t)KSZ * 1024 * DD]; // [tap][n'][k]; n'<512 Wq else Wk (BN folded)
__device__ __half g_wv[(size_t)DD * DD];          // [n][k]
__device__ __half g_wo[(size_t)DD * DD];
__device__ float  g_bqk[1024];

// ---------------- helpers ----------------
__device__ __forceinline__ uint32_t smem_u32(const void* p) {
    uint32_t a;
    asm("{ .reg .u64 t; cvta.to.shared.u64 t, %1; cvt.u32.u64 %0, t; }" : "=r"(a) : "l"(p));
    return a;
}
#define CP_ASYNC16(s, g) \
    asm volatile("cp.async.cg.shared.global [%0], [%1], 16;" :: "r"(s), "l"(g) : "memory")
#define CP_ASYNC16Z(s, g, sz) \
    asm volatile("cp.async.cg.shared.global [%0], [%1], 16, %2;" :: "r"(s), "l"(g), "r"(sz) : "memory")
#define CP_COMMIT()  asm volatile("cp.async.commit_group;" ::: "memory")
#define CP_WAIT1()   asm volatile("cp.async.wait_group 1;" ::: "memory")
#define CP_WAIT0()   asm volatile("cp.async.wait_group 0;" ::: "memory")
#define LDMX4(r0, r1, r2, r3, a) \
    asm volatile("ldmatrix.sync.aligned.m8n8.x4.shared.b16 {%0,%1,%2,%3}, [%4];" \
        : "=r"(r0), "=r"(r1), "=r"(r2), "=r"(r3) : "r"(a))
#define LDMX4T(r0, r1, r2, r3, a) \
    asm volatile("ldmatrix.sync.aligned.m8n8.x4.trans.shared.b16 {%0,%1,%2,%3}, [%4];" \
        : "=r"(r0), "=r"(r1), "=r"(r2), "=r"(r3) : "r"(a))
#define MMA16816(c, a, b) \
    asm volatile("mma.sync.aligned.m16n8k16.row.col.f32.f16.f16.f32 " \
        "{%0,%1,%2,%3}, {%4,%5,%6,%7}, {%8,%9}, {%0,%1,%2,%3};" \
        : "+f"((c)[0]), "+f"((c)[1]), "+f"((c)[2]), "+f"((c)[3]) \
        : "r"((a)[0]), "r"((a)[1]), "r"((a)[2]), "r"((a)[3]), "r"((b)[0]), "r"((b)[1]))

// ---------------- prep kernels ----------------
__global__ void x_to_half(const float* __restrict__ X, __half* __restrict__ Y)
{
    size_t i = ((size_t)blockIdx.x * 256 + threadIdx.x) * 8;
    if (i >= (size_t)MM * DD) return;
    float4 v0 = *(const float4*)(X + i);
    float4 v1 = *(const float4*)(X + i + 4);
    __half2 h0 = __floats2half2_rn(v0.x, v0.y);
    __half2 h1 = __floats2half2_rn(v0.z, v0.w);
    __half2 h2 = __floats2half2_rn(v1.x, v1.y);
    __half2 h3 = __floats2half2_rn(v1.z, v1.w);
    uint4 o = make_uint4(*(uint32_t*)&h0, *(uint32_t*)&h1, *(uint32_t*)&h2, *(uint32_t*)&h3);
    *(uint4*)(Y + i) = o;
}

__global__ void repack_conv_qk(const float* __restrict__ Wq, const float* __restrict__ gq, const float* __restrict__ vq,
                               const float* __restrict__ Wk, const float* __restrict__ gk, const float* __restrict__ vk,
                               __half* __restrict__ dst)
{
    int idx = blockIdx.x * 256 + threadIdx.x;
    if (idx >= KSZ * 1024 * DD) return;
    int k   = idx & (DD - 1);
    int np  = (idx >> 9) & 1023;
    int tap = idx >> 19;
    float w, scale;
    if (np < 512) {
        scale = gq[np] * rsqrtf(vq[np] + EPSBN);
        w = Wq[((size_t)np * DD + k) * KSZ + tap];
    } else {
        int n = np - 512;
        scale = gk[n] * rsqrtf(vk[n] + EPSBN);
        w = Wk[((size_t)n * DD + k) * KSZ + tap];
    }
    dst[idx] = __float2half_rn(w * scale);
}

__global__ void fold_bias_qk(const float* __restrict__ bq, const float* __restrict__ gq, const float* __restrict__ betaq,
                             const float* __restrict__ mq, const float* __restrict__ vq,
                             const float* __restrict__ bk, const float* __restrict__ gk, const float* __restrict__ betak,
                             const float* __restrict__ mk, const float* __restrict__ vk,
                             float* __restrict__ dst)
{
    int o = blockIdx.x * 256 + threadIdx.x;
    if (o >= 1024) return;
    if (o < 512) {
        float s = gq[o] * rsqrtf(vq[o] + EPSBN);
        dst[o] = (bq[o] - mq[o]) * s + betaq[o];
    } else {
        int n = o - 512;
        float s = gk[n] * rsqrtf(vk[n] + EPSBN);
        dst[o] = (bk[n] - mk[n]) * s + betak[n];
    }
}

__global__ void w_to_half(const float* __restrict__ Wv, const float* __restrict__ Wo,
                          __half* __restrict__ dv, __half* __restrict__ dw)
{
    int i = blockIdx.x * 256 + threadIdx.x;
    if (i < DD * DD) dv[i] = __float2half_rn(Wv[i]);
    else if (i < 2 * DD * DD) dw[i - DD * DD] = __float2half_rn(Wo[i - DD * DD]);
}

// ---------------- fp16 mma.sync GEMM: 256x128 tile, fused conv taps, stacked QK ----------------
#define MTILE 256
#define NTILE 128
#define KCH 32
#define HPITCH 40
#define A_BYTES (MTILE * HPITCH * 2)    // 20480
#define B_BYTES (NTILE * HPITCH * 2)    // 10240
#define STG_BYTES (A_BYTES + B_BYTES)   // 30720
#define NSTAGE 3
#define GEMM_SMEM (NSTAGE * STG_BYTES)  // 92160

template<int TAPS, typename OT>
__global__ void __launch_bounds__(256) gemm_h(
    const __half* __restrict__ A, const __half* __restrict__ Bt,
    const float* __restrict__ bias, OT* __restrict__ Cq, OT* __restrict__ Ck)
{
    extern __shared__ char smc[];

    const int tid  = threadIdx.x;
    const int lane = tid & 31;
    const int wid  = tid >> 5;
    const int warpM = (wid & 3) * 64;
    const int warpN = (wid >> 2) * 64;
    const int r4  = lane >> 2;
    const int c2  = lane & 3;
    const int mat = lane >> 3;
    const int r8  = lane & 7;

    const int bnb = blockIdx.x;
    const int bty = blockIdx.y;
    const size_t m0 = (size_t)bty * MTILE;

    const uint32_t sbase = smem_u32(smc);

    const uint32_t aoff0 = (uint32_t)(((warpM + ((mat & 1) << 3) + r8) * HPITCH + ((mat >> 1) << 3)) * 2);
    const uint32_t boff0 = (uint32_t)(A_BYTES + ((warpN + ((mat >> 1) << 3) + r8) * HPITCH + ((mat & 1) << 3)) * 2);

    float acc[4][8][4];
#pragma unroll
    for (int mt = 0; mt < 4; mt++)
#pragma unroll
        for (int nt = 0; nt < 8; nt++)
#pragma unroll
            for (int i = 0; i < 4; i++) acc[mt][nt][i] = 0.f;

    const int NCH = TAPS * (DD / KCH);

    auto issue_load = [&](int ci, int stg) {
        const int ti = ci >> 4;
        const int kc = ci & 15;
        const int s  = (TAPS == 3) ? (2 - ti) : 0;
        const __half* ap = A + (m0 - (size_t)s * NV) * DD + kc * KCH;
        const __half* bp = Bt + ((TAPS == 3) ? (size_t)ti * 1024 * DD : 0)
                               + ((size_t)bnb * NTILE) * DD + kc * KCH;
        const uint32_t st = sbase + (uint32_t)stg * STG_BYTES;
#pragma unroll
        for (int p = 0; p < 4; p++) {
            int idx = tid + 256 * p;
            int row = idx >> 2;
            int q   = idx & 3;
            uint32_t so = st + (uint32_t)(row * HPITCH + q * 8) * 2u;
            if (TAPS == 3) {
                int tloc = (int)((2 * bty + (row >> 7)) & 63);
                uint32_t sz = (tloc >= s) ? 16u : 0u;
                const __half* src = (tloc >= s) ? (ap + (size_t)row * DD + q * 8) : A;
                CP_ASYNC16Z(so, src, sz);
            } else {
                CP_ASYNC16(so, ap + (size_t)row * DD + q * 8);
            }
        }
#pragma unroll
        for (int p = 0; p < 2; p++) {
            int idx = tid + 256 * p;
            int row = idx >> 2;
            int q   = idx & 3;
            uint32_t so = st + (uint32_t)A_BYTES + (uint32_t)(row * HPITCH + q * 8) * 2u;
            CP_ASYNC16(so, bp + (size_t)row * DD + q * 8);
        }
        CP_COMMIT();
    };

    auto compute = [&](int stg) {
        const uint32_t st = sbase + (uint32_t)stg * STG_BYTES;
        const uint32_t abase = st + aoff0;
        const uint32_t bbase = st + boff0;
#pragma unroll
        for (int ks = 0; ks < 2; ks++) {
            uint32_t af[4][4], bf[8][2];
#pragma unroll
            for (int mt = 0; mt < 4; mt++)
                LDMX4(af[mt][0], af[mt][1], af[mt][2], af[mt][3],
                      abase + (uint32_t)((mt * 16 * HPITCH + ks * 16) * 2));
#pragma unroll
            for (int np = 0; np < 4; np++)
                LDMX4(bf[2*np][0], bf[2*np][1], bf[2*np+1][0], bf[2*np+1][1],
                      bbase + (uint32_t)((np * 16 * HPITCH + ks * 16) * 2));
#pragma unroll
            for (int mt = 0; mt < 4; mt++)
#pragma unroll
                for (int nt = 0; nt < 8; nt++)
                    MMA16816(acc[mt][nt], af[mt], bf[nt]);
        }
    };

    issue_load(0, 0);
    issue_load(1, 1);
    for (int ci = 0; ci < NCH; ci++) {
        if (ci + 1 < NCH) CP_WAIT1(); else CP_WAIT0();
        __syncthreads();
        compute(ci % NSTAGE);
        __syncthreads();
        if (ci + 2 < NCH) issue_load(ci + 2, (ci + 2) % NSTAGE);
    }

    // ---- epilogue ----
    OT* C;
    int cb;
    if (TAPS == 3 && bnb >= 4) { C = Ck; cb = bnb * NTILE - 512; }
    else                       { C = Cq; cb = bnb * NTILE; }
    const float* bp = bias + bnb * NTILE;

#pragma unroll
    for (int mt = 0; mt < 4; mt++) {
        const size_t rw = m0 + warpM + mt * 16 + r4;
#pragma unroll
        for (int nt = 0; nt < 8; nt++) {
            const int cl = warpN + nt * 8 + 2 * c2;
            const float bx = bp[cl], by = bp[cl + 1];
            float x0 = acc[mt][nt][0] + bx, y0 = acc[mt][nt][1] + by;
            float x1 = acc[mt][nt][2] + bx, y1 = acc[mt][nt][3] + by;
            if constexpr (sizeof(OT) == 2) {
                __half2 h0 = __floats2half2_rn(x0, y0);
                __half2 h1 = __floats2half2_rn(x1, y1);
                *(uint32_t*)((__half*)C + rw       * DD + cb + cl) = *(uint32_t*)&h0;
                *(uint32_t*)((__half*)C + (rw + 8) * DD + cb + cl) = *(uint32_t*)&h1;
            } else {
                *(float2*)((float*)C + rw       * DD + cb + cl) = make_float2(x0, y0);
                *(float2*)((float*)C + (rw + 8) * DD + cb + cl) = make_float2(x1, y1);
            }
        }
    }
}

// ---------------- tensor-core attention: one block per (b, n, h); 128 thr, T=64, DH=64 ----------------
// S = Q K^T (mma fp16, fp32 acc), softmax in registers, O = P V (P re-packed from S acc).
#define APIT 72                                    // halves per smem row
#define ATTN_SMEM (3 * 64 * APIT * 2)              // 27648 B

__global__ void __launch_bounds__(128) attn_tc(
    const __half* __restrict__ Q, const __half* __restrict__ K,
    const __half* __restrict__ V, __half* __restrict__ O)
{
    extern __shared__ __align__(16) __half smh[];
    __half* Qs = smh;               // [64][APIT]
    __half* Ks = smh + 64 * APIT;
    __half* Vs = smh + 2 * 64 * APIT;

    const int tid  = threadIdx.x;
    const int lane = tid & 31;
    const int w    = tid >> 5;      // warp 0..3 -> rows 16w..16w+15
    const int mat  = lane >> 3;
    const int r8   = lane & 7;
    const int qr   = lane >> 2;     // quad row 0..7
    const int qc   = lane & 3;      // quad col 0..3

    const int hid = blockIdx.x;
    const int h = hid & 7;
    const int n = (hid >> 3) & 127;
    const int b = hid >> 10;
    const size_t base = (((size_t)b * TT) * NV + n) * DD + h * DH;
    const size_t rstride = (size_t)NV * DD;

    // load Q,K,V tiles: 64 rows x 64 halves each
#pragma unroll
    for (int p = 0; p < 4; p++) {
        int idx = tid + 128 * p;
        int row = idx >> 3, q = idx & 7;
        size_t g = base + (size_t)row * rstride + q * 8;
        int so = row * APIT + q * 8;
        *(uint4*)(Qs + so) = *(const uint4*)(Q + g);
        *(uint4*)(Ks + so) = *(const uint4*)(K + g);
        *(uint4*)(Vs + so) = *(const uint4*)(V + g);
    }
    __syncthreads();

    const uint32_t sQ = smem_u32(Qs);
    const uint32_t sK = smem_u32(Ks);
    const uint32_t sV = smem_u32(Vs);

    // ---- S = Q K^T ----
    float acc[8][4];
#pragma unroll
    for (int nt = 0; nt < 8; nt++)
#pragma unroll
        for (int i = 0; i < 4; i++) acc[nt][i] = 0.f;

    const uint32_t aoff = sQ + (uint32_t)(((16 * w + ((mat & 1) << 3) + r8) * APIT + ((mat >> 1) << 3)) * 2);
    const uint32_t koff = sK + (uint32_t)(((((mat >> 1) << 3) + r8) * APIT + ((mat & 1) << 3)) * 2);

#pragma unroll
    for (int ks = 0; ks < 4; ks++) {
        uint32_t af[4], bf[8][2];
        LDMX4(af[0], af[1], af[2], af[3], aoff + (uint32_t)(ks * 32));
#pragma unroll
        for (int np = 0; np < 4; np++)
            LDMX4(bf[2*np][0], bf[2*np][1], bf[2*np+1][0], bf[2*np+1][1],
                  koff + (uint32_t)((np * 16 * APIT + ks * 16) * 2));
#pragma unroll
        for (int nt = 0; nt < 8; nt++)
            MMA16816(acc[nt], af, bf[nt]);
    }

    // ---- softmax over 64 cols (rows r=16w+qr and r+8) ----
    float mx0 = -1e30f, mx1 = -1e30f;
#pragma unroll
    for (int nt = 0; nt < 8; nt++) {
#pragma unroll
        for (int i = 0; i < 4; i++) acc[nt][i] *= 0.125f;
        mx0 = fmaxf(mx0, fmaxf(acc[nt][0], acc[nt][1]));
        mx1 = fmaxf(mx1, fmaxf(acc[nt][2], acc[nt][3]));
    }
    mx0 = fmaxf(mx0, __shfl_xor_sync(0xffffffff, mx0, 1));
    mx0 = fmaxf(mx0, __shfl_xor_sync(0xffffffff, mx0, 2));
    mx1 = fmaxf(mx1, __shfl_xor_sync(0xffffffff, mx1, 1));
    mx1 = fmaxf(mx1, __shfl_xor_sync(0xffffffff, mx1, 2));

    float sum0 = 0.f, sum1 = 0.f;
#pragma unroll
    for (int nt = 0; nt < 8; nt++) {
        acc[nt][0] = __expf(acc[nt][0] - mx0);
        acc[nt][1] = __expf(acc[nt][1] - mx0);
        acc[nt][2] = __expf(acc[nt][2] - mx1);
        acc[nt][3] = __expf(acc[nt][3] - mx1);
        sum0 += acc[nt][0] + acc[nt][1];
        sum1 += acc[nt][2] + acc[nt][3];
    }
    sum0 += __shfl_xor_sync(0xffffffff, sum0, 1);
    sum0 += __shfl_xor_sync(0xffffffff, sum0, 2);
    sum1 += __shfl_xor_sync(0xffffffff, sum1, 1);
    sum1 += __shfl_xor_sync(0xffffffff, sum1, 2);
    const float inv0 = 1.f / sum0, inv1 = 1.f / sum1;

    // ---- O = P V ----
    float acco[8][4];
#pragma unroll
    for (int nt = 0; nt < 8; nt++)
#pragma unroll
        for (int i = 0; i < 4; i++) acco[nt][i] = 0.f;

    const uint32_t voff = sV + (uint32_t)((((mat & 1) * 8 + r8) * APIT + ((mat >> 1) << 3)) * 2);

#pragma unroll
    for (int kt = 0; kt < 4; kt++) {
        // A fragment of P from S accumulators (C->A layout identity)
        uint32_t af[4];
        __half2 p0 = __floats2half2_rn(acc[2*kt][0]   * inv0, acc[2*kt][1]   * inv0);
        __half2 p1 = __floats2half2_rn(acc[2*kt][2]   * inv1, acc[2*kt][3]   * inv1);
        __half2 p2 = __floats2half2_rn(acc[2*kt+1][0] * inv0, acc[2*kt+1][1] * inv0);
        __half2 p3 = __floats2half2_rn(acc[2*kt+1][2] * inv1, acc[2*kt+1][3] * inv1);
        af[0] = *(uint32_t*)&p0; af[1] = *(uint32_t*)&p1;
        af[2] = *(uint32_t*)&p2; af[3] = *(uint32_t*)&p3;

#pragma unroll
        for (int dp = 0; dp < 4; dp++) {
            uint32_t bf0[2], bf1[2];
            LDMX4T(bf0[0], bf0[1], bf1[0], bf1[1],
                   voff + (uint32_t)((kt * 16 * APIT + dp * 16) * 2));
            MMA16816(acco[2*dp],     af, bf0);
            MMA16816(acco[2*dp + 1], af, bf1);
        }
    }

    // ---- store O (fp16, feeds O-projection) ----
    const size_t row0 = base + (size_t)(16 * w + qr) * rstride;
    const size_t row1 = row0 + 8 * rstride;
#pragma unroll
    for (int nt = 0; nt < 8; nt++) {
        int col = nt * 8 + 2 * qc;
        __half2 h0 = __floats2half2_rn(acco[nt][0], acco[nt][1]);
        __half2 h1 = __floats2half2_rn(acco[nt][2], acco[nt][3]);
        *(uint32_t*)(O + row0 + col) = *(uint32_t*)&h0;
        *(uint32_t*)(O + row1 + col) = *(uint32_t*)&h1;
    }
}

// ---------------- launch ----------------
extern "C" void kernel_launch(void* const* d_in, const int* in_sizes, int n_in,
                              void* d_out, int out_size)
{
    const float* X     = (const float*)d_in[0];
    const float* Wq    = (const float*)d_in[1];
    const float* bq    = (const float*)d_in[2];
    const float* gq    = (const float*)d_in[3];
    const float* betaq = (const float*)d_in[4];
    const float* mq    = (const float*)d_in[5];
    const float* vq    = (const float*)d_in[6];
    const float* Wk    = (const float*)d_in[7];
    const float* bk    = (const float*)d_in[8];
    const float* gk    = (const float*)d_in[9];
    const float* betak = (const float*)d_in[10];
    const float* mk    = (const float*)d_in[11];
    const float* vk    = (const float*)d_in[12];
    const float* Wv    = (const float*)d_in[13];
    const float* bv    = (const float*)d_in[14];
    const float* Wo    = (const float*)d_in[15];
    const float* bo    = (const float*)d_in[16];
    float* out = (float*)d_out;

    __half *p_xh, *p_qh, *p_kh, *p_vh, *p_ao, *p_wqk, *p_wv, *p_wo;
    float *p_bqk;
    cudaGetSymbolAddress((void**)&p_xh,  g_xh);
    cudaGetSymbolAddress((void**)&p_qh,  g_qh);
    cudaGetSymbolAddress((void**)&p_kh,  g_kh);
    cudaGetSymbolAddress((void**)&p_vh,  g_vh);
    cudaGetSymbolAddress((void**)&p_ao,  g_ao);
    cudaGetSymbolAddress((void**)&p_wqk, g_wqk);
    cudaGetSymbolAddress((void**)&p_wv,  g_wv);
    cudaGetSymbolAddress((void**)&p_wo,  g_wo);
    cudaGetSymbolAddress((void**)&p_bqk, g_bqk);

    // 1) fp16 operand prep
    x_to_half<<<(MM * DD / 8 + 255) / 256, 256>>>(X, p_xh);
    repack_conv_qk<<<(KSZ * 1024 * DD + 255) / 256, 256>>>(Wq, gq, vq, Wk, gk, vk, p_wqk);
    fold_bias_qk<<<4, 256>>>(bq, gq, betaq, mq, vq, bk, gk, betak, mk, vk, p_bqk);
    w_to_half<<<(2 * DD * DD + 255) / 256, 256>>>(Wv, Wo, p_wv, p_wo);

    // 2) projections (fp16 tensor cores); Q/K/V written fp16
    cudaFuncSetAttribute(gemm_h<3, __half>, cudaFuncAttributeMaxDynamicSharedMemorySize, GEMM_SMEM);
    cudaFuncSetAttribute(gemm_h<1, __half>, cudaFuncAttributeMaxDynamicSharedMemorySize, GEMM_SMEM);
    cudaFuncSetAttribute(gemm_h<1, float>,  cudaFuncAttributeMaxDynamicSharedMemorySize, GEMM_SMEM);
    dim3 gqk(1024 / NTILE, MM / MTILE);   // (8, 256) — fused Q+K
    dim3 gl (DD / NTILE,   MM / MTILE);   // (4, 256)
    gemm_h<3, __half><<<gqk, 256, GEMM_SMEM>>>(p_xh, p_wqk, p_bqk, p_qh, p_kh);
    gemm_h<1, __half><<<gl,  256, GEMM_SMEM>>>(p_xh, p_wv, bv, p_vh, nullptr);

    // 3) tensor-core attention (8192 heads)
    cudaFuncSetAttribute(attn_tc, cudaFuncAttributeMaxDynamicSharedMemorySize, ATTN_SMEM);
    attn_tc<<<BB * NV * KH, 128, ATTN_SMEM>>>(p_qh, p_kh, p_vh, p_ao);

    // 4) output projection -> d_out (fp32)
    gemm_h<1, float><<<gl, 256, GEMM_SMEM>>>(p_ao, p_wo, bo, out, nullptr);
}

// round 13
// speedup vs baseline: 5.5189x; 1.0184x over previous
#include <cuda_runtime.h>
#include <cuda_fp16.h>
#include <cstdint>
#include <cstddef>

// ---------------- problem constants ----------------
#define BB 8
#define TT 64
#define NV 128
#define DD 512
#define KH 8
#define DH 64
#define KSZ 3
#define MM (BB*TT*NV)          // 65536 tokens
#define EPSBN 1e-5f

// ---------------- device scratch ----------------
__device__ __half g_xh[(size_t)MM * DD];          // fp16 X
__device__ __half g_qh[(size_t)MM * DD];          // fp16 Q
__device__ __half g_kh[(size_t)MM * DD];          // fp16 K
__device__ __half g_vh[(size_t)MM * DD];          // fp16 V
__device__ __half g_ao[(size_t)MM * DD];          // fp16 attention out
__device__ __half g_wqk[(size_t)KSZ * 1024 * DD]; // [tap][n'][k]; n'<512 Wq else Wk (BN folded)
__device__ __half g_wv[(size_t)DD * DD];          // [n][k]
__device__ __half g_wo[(size_t)DD * DD];
__device__ float  g_bqk[1024];

// ---------------- helpers ----------------
__device__ __forceinline__ uint32_t smem_u32(const void* p) {
    uint32_t a;
    asm("{ .reg .u64 t; cvta.to.shared.u64 t, %1; cvt.u32.u64 %0, t; }" : "=r"(a) : "l"(p));
    return a;
}
#define CP_ASYNC16(s, g) \
    asm volatile("cp.async.cg.shared.global [%0], [%1], 16;" :: "r"(s), "l"(g) : "memory")
#define CP_ASYNC16Z(s, g, sz) \
    asm volatile("cp.async.cg.shared.global [%0], [%1], 16, %2;" :: "r"(s), "l"(g), "r"(sz) : "memory")
#define CP_COMMIT()  asm volatile("cp.async.commit_group;" ::: "memory")
#define CP_WAIT1()   asm volatile("cp.async.wait_group 1;" ::: "memory")
#define CP_WAIT0()   asm volatile("cp.async.wait_group 0;" ::: "memory")
#define LDMX4(r0, r1, r2, r3, a) \
    asm volatile("ldmatrix.sync.aligned.m8n8.x4.shared.b16 {%0,%1,%2,%3}, [%4];" \
        : "=r"(r0), "=r"(r1), "=r"(r2), "=r"(r3) : "r"(a))
#define LDMX4T(r0, r1, r2, r3, a) \
    asm volatile("ldmatrix.sync.aligned.m8n8.x4.trans.shared.b16 {%0,%1,%2,%3}, [%4];" \
        : "=r"(r0), "=r"(r1), "=r"(r2), "=r"(r3) : "r"(a))
#define MMA16816(c, a, b) \
    asm volatile("mma.sync.aligned.m16n8k16.row.col.f32.f16.f16.f32 " \
        "{%0,%1,%2,%3}, {%4,%5,%6,%7}, {%8,%9}, {%0,%1,%2,%3};" \
        : "+f"((c)[0]), "+f"((c)[1]), "+f"((c)[2]), "+f"((c)[3]) \
        : "r"((a)[0]), "r"((a)[1]), "r"((a)[2]), "r"((a)[3]), "r"((b)[0]), "r"((b)[1]))

// ---------------- prep kernels ----------------
__global__ void x_to_half(const float* __restrict__ X, __half* __restrict__ Y)
{
    size_t i = ((size_t)blockIdx.x * 256 + threadIdx.x) * 8;
    if (i >= (size_t)MM * DD) return;
    float4 v0 = *(const float4*)(X + i);
    float4 v1 = *(const float4*)(X + i + 4);
    __half2 h0 = __floats2half2_rn(v0.x, v0.y);
    __half2 h1 = __floats2half2_rn(v0.z, v0.w);
    __half2 h2 = __floats2half2_rn(v1.x, v1.y);
    __half2 h3 = __floats2half2_rn(v1.z, v1.w);
    uint4 o = make_uint4(*(uint32_t*)&h0, *(uint32_t*)&h1, *(uint32_t*)&h2, *(uint32_t*)&h3);
    *(uint4*)(Y + i) = o;
}

// single merged weight/bias prep:
//  range 0:                 KSZ*1024*512   -> g_wqk (conv weights, BN folded)
//  range 1:  + 512*512      -> g_wv
//  range 2:  + 512*512      -> g_wo
//  range 3:  + 1024         -> g_bqk (folded bias)
#define R0 (KSZ * 1024 * DD)
#define R1 (R0 + DD * DD)
#define R2 (R1 + DD * DD)
#define R3 (R2 + 1024)
__global__ void prep_weights(
    const float* __restrict__ Wq, const float* __restrict__ gq, const float* __restrict__ vq,
    const float* __restrict__ Wk, const float* __restrict__ gk, const float* __restrict__ vk,
    const float* __restrict__ Wv, const float* __restrict__ Wo,
    const float* __restrict__ bq, const float* __restrict__ betaq, const float* __restrict__ mq,
    const float* __restrict__ bk, const float* __restrict__ betak, const float* __restrict__ mk,
    __half* __restrict__ dqk, __half* __restrict__ dv, __half* __restrict__ dw,
    float* __restrict__ dbias)
{
    int idx = blockIdx.x * 256 + threadIdx.x;
    if (idx < R0) {
        int k   = idx & (DD - 1);
        int np  = (idx >> 9) & 1023;
        int tap = idx >> 19;
        float w, scale;
        if (np < 512) {
            scale = gq[np] * rsqrtf(vq[np] + EPSBN);
            w = Wq[((size_t)np * DD + k) * KSZ + tap];
        } else {
            int n = np - 512;
            scale = gk[n] * rsqrtf(vk[n] + EPSBN);
            w = Wk[((size_t)n * DD + k) * KSZ + tap];
        }
        dqk[idx] = __float2half_rn(w * scale);
    } else if (idx < R1) {
        int i = idx - R0;
        dv[i] = __float2half_rn(Wv[i]);
    } else if (idx < R2) {
        int i = idx - R1;
        dw[i] = __float2half_rn(Wo[i]);
    } else if (idx < R3) {
        int o = idx - R2;
        if (o < 512) {
            float s = gq[o] * rsqrtf(vq[o] + EPSBN);
            dbias[o] = (bq[o] - mq[o]) * s + betaq[o];
        } else {
            int n = o - 512;
            float s = gk[n] * rsqrtf(vk[n] + EPSBN);
            dbias[o] = (bk[n] - mk[n]) * s + betak[n];
        }
    }
}

// ---------------- fp16 mma.sync GEMM: 256x128 tile, fused conv taps, stacked QK ----------------
#define MTILE 256
#define NTILE 128
#define KCH 32
#define HPITCH 40
#define A_BYTES (MTILE * HPITCH * 2)    // 20480
#define B_BYTES (NTILE * HPITCH * 2)    // 10240
#define STG_BYTES (A_BYTES + B_BYTES)   // 30720
#define NSTAGE 3
#define GEMM_SMEM (NSTAGE * STG_BYTES)  // 92160

template<int TAPS, typename OT>
__global__ void __launch_bounds__(256) gemm_h(
    const __half* __restrict__ A, const __half* __restrict__ Bt,
    const float* __restrict__ bias, OT* __restrict__ Cq, OT* __restrict__ Ck)
{
    extern __shared__ char smc[];

    const int tid  = threadIdx.x;
    const int lane = tid & 31;
    const int wid  = tid >> 5;
    const int warpM = (wid & 3) * 64;
    const int warpN = (wid >> 2) * 64;
    const int r4  = lane >> 2;
    const int c2  = lane & 3;
    const int mat = lane >> 3;
    const int r8  = lane & 7;

    const int bnb = blockIdx.x;
    const int bty = blockIdx.y;
    const size_t m0 = (size_t)bty * MTILE;

    const uint32_t sbase = smem_u32(smc);

    const uint32_t aoff0 = (uint32_t)(((warpM + ((mat & 1) << 3) + r8) * HPITCH + ((mat >> 1) << 3)) * 2);
    const uint32_t boff0 = (uint32_t)(A_BYTES + ((warpN + ((mat >> 1) << 3) + r8) * HPITCH + ((mat & 1) << 3)) * 2);

    float acc[4][8][4];
#pragma unroll
    for (int mt = 0; mt < 4; mt++)
#pragma unroll
        for (int nt = 0; nt < 8; nt++)
#pragma unroll
            for (int i = 0; i < 4; i++) acc[mt][nt][i] = 0.f;

    const int NCH = TAPS * (DD / KCH);

    auto issue_load = [&](int ci, int stg) {
        const int ti = ci >> 4;
        const int kc = ci & 15;
        const int s  = (TAPS == 3) ? (2 - ti) : 0;
        const __half* ap = A + (m0 - (size_t)s * NV) * DD + kc * KCH;
        const __half* bp = Bt + ((TAPS == 3) ? (size_t)ti * 1024 * DD : 0)
                               + ((size_t)bnb * NTILE) * DD + kc * KCH;
        const uint32_t st = sbase + (uint32_t)stg * STG_BYTES;
#pragma unroll
        for (int p = 0; p < 4; p++) {
            int idx = tid + 256 * p;
            int row = idx >> 2;
            int q   = idx & 3;
            uint32_t so = st + (uint32_t)(row * HPITCH + q * 8) * 2u;
            if (TAPS == 3) {
                int tloc = (int)((2 * bty + (row >> 7)) & 63);
                uint32_t sz = (tloc >= s) ? 16u : 0u;
                const __half* src = (tloc >= s) ? (ap + (size_t)row * DD + q * 8) : A;
                CP_ASYNC16Z(so, src, sz);
            } else {
                CP_ASYNC16(so, ap + (size_t)row * DD + q * 8);
            }
        }
#pragma unroll
        for (int p = 0; p < 2; p++) {
            int idx = tid + 256 * p;
            int row = idx >> 2;
            int q   = idx & 3;
            uint32_t so = st + (uint32_t)A_BYTES + (uint32_t)(row * HPITCH + q * 8) * 2u;
            CP_ASYNC16(so, bp + (size_t)row * DD + q * 8);
        }
        CP_COMMIT();
    };

    auto compute = [&](int stg) {
        const uint32_t st = sbase + (uint32_t)stg * STG_BYTES;
        const uint32_t abase = st + aoff0;
        const uint32_t bbase = st + boff0;
#pragma unroll
        for (int ks = 0; ks < 2; ks++) {
            uint32_t af[4][4], bf[8][2];
#pragma unroll
            for (int mt = 0; mt < 4; mt++)
                LDMX4(af[mt][0], af[mt][1], af[mt][2], af[mt][3],
                      abase + (uint32_t)((mt * 16 * HPITCH + ks * 16) * 2));
#pragma unroll
            for (int np = 0; np < 4; np++)
                LDMX4(bf[2*np][0], bf[2*np][1], bf[2*np+1][0], bf[2*np+1][1],
                      bbase + (uint32_t)((np * 16 * HPITCH + ks * 16) * 2));
#pragma unroll
            for (int mt = 0; mt < 4; mt++)
#pragma unroll
                for (int nt = 0; nt < 8; nt++)
                    MMA16816(acc[mt][nt], af[mt], bf[nt]);
        }
    };

    // ---- 3-stage pipeline, ONE barrier per chunk ----
    // Safety: issue_load(ci+2) overwrites stage (ci-1)%3; every warp consumed
    // that stage in compute(ci-1), which precedes bar(ci) in program order.
    issue_load(0, 0);
    issue_load(1, 1);
    for (int ci = 0; ci < NCH; ci++) {
        if (ci + 1 < NCH) CP_WAIT1(); else CP_WAIT0();
        __syncthreads();
        if (ci + 2 < NCH) issue_load(ci + 2, (ci + 2) % NSTAGE);
        compute(ci % NSTAGE);
    }

    // ---- epilogue ----
    OT* C;
    int cb;
    if (TAPS == 3 && bnb >= 4) { C = Ck; cb = bnb * NTILE - 512; }
    else                       { C = Cq; cb = bnb * NTILE; }
    const float* bp = bias + bnb * NTILE;

#pragma unroll
    for (int mt = 0; mt < 4; mt++) {
        const size_t rw = m0 + warpM + mt * 16 + r4;
#pragma unroll
        for (int nt = 0; nt < 8; nt++) {
            const int cl = warpN + nt * 8 + 2 * c2;
            const float bx = bp[cl], by = bp[cl + 1];
            float x0 = acc[mt][nt][0] + bx, y0 = acc[mt][nt][1] + by;
            float x1 = acc[mt][nt][2] + bx, y1 = acc[mt][nt][3] + by;
            if constexpr (sizeof(OT) == 2) {
                __half2 h0 = __floats2half2_rn(x0, y0);
                __half2 h1 = __floats2half2_rn(x1, y1);
                *(uint32_t*)((__half*)C + rw       * DD + cb + cl) = *(uint32_t*)&h0;
                *(uint32_t*)((__half*)C + (rw + 8) * DD + cb + cl) = *(uint32_t*)&h1;
            } else {
                *(float2*)((float*)C + rw       * DD + cb + cl) = make_float2(x0, y0);
                *(float2*)((float*)C + (rw + 8) * DD + cb + cl) = make_float2(x1, y1);
            }
        }
    }
}

// ---------------- tensor-core attention: one block per (b, n, h); 128 thr, T=64, DH=64 ----------------
#define APIT 72                                    // halves per smem row
#define ATTN_SMEM (3 * 64 * APIT * 2)              // 27648 B

__global__ void __launch_bounds__(128) attn_tc(
    const __half* __restrict__ Q, const __half* __restrict__ K,
    const __half* __restrict__ V, __half* __restrict__ O)
{
    extern __shared__ __align__(16) __half smh[];
    __half* Qs = smh;               // [64][APIT]
    __half* Ks = smh + 64 * APIT;
    __half* Vs = smh + 2 * 64 * APIT;

    const int tid  = threadIdx.x;
    const int lane = tid & 31;
    const int w    = tid >> 5;
    const int mat  = lane >> 3;
    const int r8   = lane & 7;
    const int qr   = lane >> 2;
    const int qc   = lane & 3;

    const int hid = blockIdx.x;
    const int h = hid & 7;
    const int n = (hid >> 3) & 127;
    const int b = hid >> 10;
    const size_t base = (((size_t)b * TT) * NV + n) * DD + h * DH;
    const size_t rstride = (size_t)NV * DD;

#pragma unroll
    for (int p = 0; p < 4; p++) {
        int idx = tid + 128 * p;
        int row = idx >> 3, q = idx & 7;
        size_t g = base + (size_t)row * rstride + q * 8;
        int so = row * APIT + q * 8;
        *(uint4*)(Qs + so) = *(const uint4*)(Q + g);
        *(uint4*)(Ks + so) = *(const uint4*)(K + g);
        *(uint4*)(Vs + so) = *(const uint4*)(V + g);
    }
    __syncthreads();

    const uint32_t sQ = smem_u32(Qs);
    const uint32_t sK = smem_u32(Ks);
    const uint32_t sV = smem_u32(Vs);

    // ---- S = Q K^T ----
    float acc[8][4];
#pragma unroll
    for (int nt = 0; nt < 8; nt++)
#pragma unroll
        for (int i = 0; i < 4; i++) acc[nt][i] = 0.f;

    const uint32_t aoff = sQ + (uint32_t)(((16 * w + ((mat & 1) << 3) + r8) * APIT + ((mat >> 1) << 3)) * 2);
    const uint32_t koff = sK + (uint32_t)(((((mat >> 1) << 3) + r8) * APIT + ((mat & 1) << 3)) * 2);

#pragma unroll
    for (int ks = 0; ks < 4; ks++) {
        uint32_t af[4], bf[8][2];
        LDMX4(af[0], af[1], af[2], af[3], aoff + (uint32_t)(ks * 32));
#pragma unroll
        for (int np = 0; np < 4; np++)
            LDMX4(bf[2*np][0], bf[2*np][1], bf[2*np+1][0], bf[2*np+1][1],
                  koff + (uint32_t)((np * 16 * APIT + ks * 16) * 2));
#pragma unroll
        for (int nt = 0; nt < 8; nt++)
            MMA16816(acc[nt], af, bf[nt]);
    }

    // ---- softmax (rows 16w+qr and +8) ----
    float mx0 = -1e30f, mx1 = -1e30f;
#pragma unroll
    for (int nt = 0; nt < 8; nt++) {
#pragma unroll
        for (int i = 0; i < 4; i++) acc[nt][i] *= 0.125f;
        mx0 = fmaxf(mx0, fmaxf(acc[nt][0], acc[nt][1]));
        mx1 = fmaxf(mx1, fmaxf(acc[nt][2], acc[nt][3]));
    }
    mx0 = fmaxf(mx0, __shfl_xor_sync(0xffffffff, mx0, 1));
    mx0 = fmaxf(mx0, __shfl_xor_sync(0xffffffff, mx0, 2));
    mx1 = fmaxf(mx1, __shfl_xor_sync(0xffffffff, mx1, 1));
    mx1 = fmaxf(mx1, __shfl_xor_sync(0xffffffff, mx1, 2));

    float sum0 = 0.f, sum1 = 0.f;
#pragma unroll
    for (int nt = 0; nt < 8; nt++) {
        acc[nt][0] = __expf(acc[nt][0] - mx0);
        acc[nt][1] = __expf(acc[nt][1] - mx0);
        acc[nt][2] = __expf(acc[nt][2] - mx1);
        acc[nt][3] = __expf(acc[nt][3] - mx1);
        sum0 += acc[nt][0] + acc[nt][1];
        sum1 += acc[nt][2] + acc[nt][3];
    }
    sum0 += __shfl_xor_sync(0xffffffff, sum0, 1);
    sum0 += __shfl_xor_sync(0xffffffff, sum0, 2);
    sum1 += __shfl_xor_sync(0xffffffff, sum1, 1);
    sum1 += __shfl_xor_sync(0xffffffff, sum1, 2);
    const float inv0 = 1.f / sum0, inv1 = 1.f / sum1;

    // ---- O = P V ----
    float acco[8][4];
#pragma unroll
    for (int nt = 0; nt < 8; nt++)
#pragma unroll
        for (int i = 0; i < 4; i++) acco[nt][i] = 0.f;

    const uint32_t voff = sV + (uint32_t)((((mat & 1) * 8 + r8) * APIT + ((mat >> 1) << 3)) * 2);

#pragma unroll
    for (int kt = 0; kt < 4; kt++) {
        uint32_t af[4];
        __half2 p0 = __floats2half2_rn(acc[2*kt][0]   * inv0, acc[2*kt][1]   * inv0);
        __half2 p1 = __floats2half2_rn(acc[2*kt][2]   * inv1, acc[2*kt][3]   * inv1);
        __half2 p2 = __floats2half2_rn(acc[2*kt+1][0] * inv0, acc[2*kt+1][1] * inv0);
        __half2 p3 = __floats2half2_rn(acc[2*kt+1][2] * inv1, acc[2*kt+1][3] * inv1);
        af[0] = *(uint32_t*)&p0; af[1] = *(uint32_t*)&p1;
        af[2] = *(uint32_t*)&p2; af[3] = *(uint32_t*)&p3;

#pragma unroll
        for (int dp = 0; dp < 4; dp++) {
            uint32_t bf0[2], bf1[2];
            LDMX4T(bf0[0], bf0[1], bf1[0], bf1[1],
                   voff + (uint32_t)((kt * 16 * APIT + dp * 16) * 2));
            MMA16816(acco[2*dp],     af, bf0);
            MMA16816(acco[2*dp + 1], af, bf1);
        }
    }

    const size_t row0 = base + (size_t)(16 * w + qr) * rstride;
    const size_t row1 = row0 + 8 * rstride;
#pragma unroll
    for (int nt = 0; nt < 8; nt++) {
        int col = nt * 8 + 2 * qc;
        __half2 h0 = __floats2half2_rn(acco[nt][0], acco[nt][1]);
        __half2 h1 = __floats2half2_rn(acco[nt][2], acco[nt][3]);
        *(uint32_t*)(O + row0 + col) = *(uint32_t*)&h0;
        *(uint32_t*)(O + row1 + col) = *(uint32_t*)&h1;
    }
}

// ---------------- launch ----------------
extern "C" void kernel_launch(void* const* d_in, const int* in_sizes, int n_in,
                              void* d_out, int out_size)
{
    const float* X     = (const float*)d_in[0];
    const float* Wq    = (const float*)d_in[1];
    const float* bq    = (const float*)d_in[2];
    const float* gq    = (const float*)d_in[3];
    const float* betaq = (const float*)d_in[4];
    const float* mq    = (const float*)d_in[5];
    const float* vq    = (const float*)d_in[6];
    const float* Wk    = (const float*)d_in[7];
    const float* bk    = (const float*)d_in[8];
    const float* gk    = (const float*)d_in[9];
    const float* betak = (const float*)d_in[10];
    const float* mk    = (const float*)d_in[11];
    const float* vk    = (const float*)d_in[12];
    const float* Wv    = (const float*)d_in[13];
    const float* bv    = (const float*)d_in[14];
    const float* Wo    = (const float*)d_in[15];
    const float* bo    = (const float*)d_in[16];
    float* out = (float*)d_out;

    __half *p_xh, *p_qh, *p_kh, *p_vh, *p_ao, *p_wqk, *p_wv, *p_wo;
    float *p_bqk;
    cudaGetSymbolAddress((void**)&p_xh,  g_xh);
    cudaGetSymbolAddress((void**)&p_qh,  g_qh);
    cudaGetSymbolAddress((void**)&p_kh,  g_kh);
    cudaGetSymbolAddress((void**)&p_vh,  g_vh);
    cudaGetSymbolAddress((void**)&p_ao,  g_ao);
    cudaGetSymbolAddress((void**)&p_wqk, g_wqk);
    cudaGetSymbolAddress((void**)&p_wv,  g_wv);
    cudaGetSymbolAddress((void**)&p_wo,  g_wo);
    cudaGetSymbolAddress((void**)&p_bqk, g_bqk);

    // 1) fp16 operand prep (2 launches)
    x_to_half<<<(MM * DD / 8 + 255) / 256, 256>>>(X, p_xh);
    prep_weights<<<(R3 + 255) / 256, 256>>>(Wq, gq, vq, Wk, gk, vk, Wv, Wo,
                                            bq, betaq, mq, bk, betak, mk,
                                            p_wqk, p_wv, p_wo, p_bqk);

    // 2) projections (fp16 tensor cores); Q/K/V written fp16
    cudaFuncSetAttribute(gemm_h<3, __half>, cudaFuncAttributeMaxDynamicSharedMemorySize, GEMM_SMEM);
    cudaFuncSetAttribute(gemm_h<1, __half>, cudaFuncAttributeMaxDynamicSharedMemorySize, GEMM_SMEM);
    cudaFuncSetAttribute(gemm_h<1, float>,  cudaFuncAttributeMaxDynamicSharedMemorySize, GEMM_SMEM);
    dim3 gqk(1024 / NTILE, MM / MTILE);   // (8, 256) — fused Q+K
    dim3 gl (DD / NTILE,   MM / MTILE);   // (4, 256)
    gemm_h<3, __half><<<gqk, 256, GEMM_SMEM>>>(p_xh, p_wqk, p_bqk, p_qh, p_kh);
    gemm_h<1, __half><<<gl,  256, GEMM_SMEM>>>(p_xh, p_wv, bv, p_vh, nullptr);

    // 3) tensor-core attention (8192 heads)
    cudaFuncSetAttribute(attn_tc, cudaFuncAttributeMaxDynamicSharedMemorySize, ATTN_SMEM);
    attn_tc<<<BB * NV * KH, 128, ATTN_SMEM>>>(p_qh, p_kh, p_vh, p_ao);

    // 4) output projection -> d_out (fp32)
    gemm_h<1, float><<<gl, 256, GEMM_SMEM>>>(p_ao, p_wo, bo, out, nullptr);
}

// round 17
// speedup vs baseline: 5.8284x; 1.0561x over previous
#include <cuda_runtime.h>
#include <cuda_fp16.h>
#include <cstdint>
#include <cstddef>

// ---------------- problem constants ----------------
#define BB 8
#define TT 64
#define NV 128
#define DD 512
#define KH 8
#define DH 64
#define KSZ 3
#define MM (BB*TT*NV)          // 65536 tokens
#define EPSBN 1e-5f

// ---------------- device scratch ----------------
__device__ __half g_xh[(size_t)MM * DD];          // fp16 X
__device__ __half g_qh[(size_t)MM * DD];          // fp16 Q
__device__ __half g_kh[(size_t)MM * DD];          // fp16 K
__device__ __half g_vh[(size_t)MM * DD];          // fp16 V
__device__ __half g_ao[(size_t)MM * DD];          // fp16 attention out
__device__ __half g_wqk[(size_t)KSZ * 1024 * DD]; // [tap][n'][k]; n'<512 Wq else Wk (BN folded)
__device__ __half g_wv[(size_t)DD * DD];          // [n][k]
__device__ __half g_wo[(size_t)DD * DD];
__device__ float  g_bqk[1024];

// ---------------- helpers ----------------
__device__ __forceinline__ uint32_t smem_u32(const void* p) {
    uint32_t a;
    asm("{ .reg .u64 t; cvta.to.shared.u64 t, %1; cvt.u32.u64 %0, t; }" : "=r"(a) : "l"(p));
    return a;
}
#define CP_ASYNC16(s, g) \
    asm volatile("cp.async.cg.shared.global [%0], [%1], 16;" :: "r"(s), "l"(g) : "memory")
#define CP_ASYNC16Z(s, g, sz) \
    asm volatile("cp.async.cg.shared.global [%0], [%1], 16, %2;" :: "r"(s), "l"(g), "r"(sz) : "memory")
#define CP_COMMIT()  asm volatile("cp.async.commit_group;" ::: "memory")
#define CP_WAIT1()   asm volatile("cp.async.wait_group 1;" ::: "memory")
#define CP_WAIT0()   asm volatile("cp.async.wait_group 0;" ::: "memory")
#define LDMX4(r0, r1, r2, r3, a) \
    asm volatile("ldmatrix.sync.aligned.m8n8.x4.shared.b16 {%0,%1,%2,%3}, [%4];" \
        : "=r"(r0), "=r"(r1), "=r"(r2), "=r"(r3) : "r"(a))
#define LDMX4T(r0, r1, r2, r3, a) \
    asm volatile("ldmatrix.sync.aligned.m8n8.x4.trans.shared.b16 {%0,%1,%2,%3}, [%4];" \
        : "=r"(r0), "=r"(r1), "=r"(r2), "=r"(r3) : "r"(a))
#define MMA16816(c, a, b) \
    asm volatile("mma.sync.aligned.m16n8k16.row.col.f32.f16.f16.f32 " \
        "{%0,%1,%2,%3}, {%4,%5,%6,%7}, {%8,%9}, {%0,%1,%2,%3};" \
        : "+f"((c)[0]), "+f"((c)[1]), "+f"((c)[2]), "+f"((c)[3]) \
        : "r"((a)[0]), "r"((a)[1]), "r"((a)[2]), "r"((a)[3]), "r"((b)[0]), "r"((b)[1]))

// ---------------- prep kernels ----------------
__global__ void x_to_half(const float* __restrict__ X, __half* __restrict__ Y)
{
    size_t i = ((size_t)blockIdx.x * 256 + threadIdx.x) * 8;
    if (i >= (size_t)MM * DD) return;
    float4 v0 = *(const float4*)(X + i);
    float4 v1 = *(const float4*)(X + i + 4);
    __half2 h0 = __floats2half2_rn(v0.x, v0.y);
    __half2 h1 = __floats2half2_rn(v0.z, v0.w);
    __half2 h2 = __floats2half2_rn(v1.x, v1.y);
    __half2 h3 = __floats2half2_rn(v1.z, v1.w);
    uint4 o = make_uint4(*(uint32_t*)&h0, *(uint32_t*)&h1, *(uint32_t*)&h2, *(uint32_t*)&h3);
    *(uint4*)(Y + i) = o;
}

// single merged weight/bias prep
#define R0 (KSZ * 1024 * DD)
#define R1 (R0 + DD * DD)
#define R2 (R1 + DD * DD)
#define R3 (R2 + 1024)
__global__ void prep_weights(
    const float* __restrict__ Wq, const float* __restrict__ gq, const float* __restrict__ vq,
    const float* __restrict__ Wk, const float* __restrict__ gk, const float* __restrict__ vk,
    const float* __restrict__ Wv, const float* __restrict__ Wo,
    const float* __restrict__ bq, const float* __restrict__ betaq, const float* __restrict__ mq,
    const float* __restrict__ bk, const float* __restrict__ betak, const float* __restrict__ mk,
    __half* __restrict__ dqk, __half* __restrict__ dv, __half* __restrict__ dw,
    float* __restrict__ dbias)
{
    int idx = blockIdx.x * 256 + threadIdx.x;
    if (idx < R0) {
        int k   = idx & (DD - 1);
        int np  = (idx >> 9) & 1023;
        int tap = idx >> 19;
        float w, scale;
        if (np < 512) {
            scale = gq[np] * rsqrtf(vq[np] + EPSBN);
            w = Wq[((size_t)np * DD + k) * KSZ + tap];
        } else {
            int n = np - 512;
            scale = gk[n] * rsqrtf(vk[n] + EPSBN);
            w = Wk[((size_t)n * DD + k) * KSZ + tap];
        }
        dqk[idx] = __float2half_rn(w * scale);
    } else if (idx < R1) {
        int i = idx - R0;
        dv[i] = __float2half_rn(Wv[i]);
    } else if (idx < R2) {
        int i = idx - R1;
        dw[i] = __float2half_rn(Wo[i]);
    } else if (idx < R3) {
        int o = idx - R2;
        if (o < 512) {
            float s = gq[o] * rsqrtf(vq[o] + EPSBN);
            dbias[o] = (bq[o] - mq[o]) * s + betaq[o];
        } else {
            int n = o - 512;
            float s = gk[n] * rsqrtf(vk[n] + EPSBN);
            dbias[o] = (bk[n] - mk[n]) * s + betak[n];
        }
    }
}

// ---------------- fp16 mma.sync GEMM: 256x128 tile, 512 thr (16 warps, warptile 64x32) ----------------
#define MTILE 256
#define NTILE 128
#define KCH 32
#define HPITCH 40
#define A_BYTES (MTILE * HPITCH * 2)    // 20480
#define B_BYTES (NTILE * HPITCH * 2)    // 10240
#define STG_BYTES (A_BYTES + B_BYTES)   // 30720
#define NSTAGE 3
#define GEMM_SMEM (NSTAGE * STG_BYTES)  // 92160
#define GTHREADS 512

template<int TAPS, typename OT>
__global__ void __launch_bounds__(GTHREADS, 1) gemm_h(
    const __half* __restrict__ A, const __half* __restrict__ Bt,
    const float* __restrict__ bias, OT* __restrict__ Cq, OT* __restrict__ Ck)
{
    extern __shared__ char smc[];

    const int tid  = threadIdx.x;
    const int lane = tid & 31;
    const int wid  = tid >> 5;
    const int warpM = (wid & 3) * 64;     // 4 warps along M (256)
    const int warpN = (wid >> 2) * 32;    // 4 warps along N (128)
    const int r4  = lane >> 2;
    const int c2  = lane & 3;
    const int mat = lane >> 3;
    const int r8  = lane & 7;

    const int bnb = blockIdx.x;
    const int bty = blockIdx.y;
    const size_t m0 = (size_t)bty * MTILE;

    const uint32_t sbase = smem_u32(smc);

    const uint32_t aoff0 = (uint32_t)(((warpM + ((mat & 1) << 3) + r8) * HPITCH + ((mat >> 1) << 3)) * 2);
    const uint32_t boff0 = (uint32_t)(A_BYTES + ((warpN + ((mat >> 1) << 3) + r8) * HPITCH + ((mat & 1) << 3)) * 2);

    float acc[4][4][4];
#pragma unroll
    for (int mt = 0; mt < 4; mt++)
#pragma unroll
        for (int nt = 0; nt < 4; nt++)
#pragma unroll
            for (int i = 0; i < 4; i++) acc[mt][nt][i] = 0.f;

    const int NCH = TAPS * (DD / KCH);

    auto issue_load = [&](int ci, int stg) {
        const int ti = ci >> 4;
        const int kc = ci & 15;
        const int s  = (TAPS == 3) ? (2 - ti) : 0;
        const __half* ap = A + (m0 - (size_t)s * NV) * DD + kc * KCH;
        const __half* bp = Bt + ((TAPS == 3) ? (size_t)ti * 1024 * DD : 0)
                               + ((size_t)bnb * NTILE) * DD + kc * KCH;
        const uint32_t st = sbase + (uint32_t)stg * STG_BYTES;
        // A: 256 rows x 4 quads = 1024 quads, 2 per thread
#pragma unroll
        for (int p = 0; p < 2; p++) {
            int idx = tid + GTHREADS * p;
            int row = idx >> 2;
            int q   = idx & 3;
            uint32_t so = st + (uint32_t)(row * HPITCH + q * 8) * 2u;
            if (TAPS == 3) {
                int tloc = (int)((2 * bty + (row >> 7)) & 63);
                uint32_t sz = (tloc >= s) ? 16u : 0u;
                const __half* src = (tloc >= s) ? (ap + (size_t)row * DD + q * 8) : A;
                CP_ASYNC16Z(so, src, sz);
            } else {
                CP_ASYNC16(so, ap + (size_t)row * DD + q * 8);
            }
        }
        // B: 128 rows x 4 quads = 512 quads, 1 per thread
        {
            int row = tid >> 2;
            int q   = tid & 3;
            uint32_t so = st + (uint32_t)A_BYTES + (uint32_t)(row * HPITCH + q * 8) * 2u;
            CP_ASYNC16(so, bp + (size_t)row * DD + q * 8);
        }
        CP_COMMIT();
    };

    auto compute = [&](int stg) {
        const uint32_t st = sbase + (uint32_t)stg * STG_BYTES;
        const uint32_t abase = st + aoff0;
        const uint32_t bbase = st + boff0;
#pragma unroll
        for (int ks = 0; ks < 2; ks++) {
            uint32_t af[4][4], bf[4][2];
#pragma unroll
            for (int mt = 0; mt < 4; mt++)
                LDMX4(af[mt][0], af[mt][1], af[mt][2], af[mt][3],
                      abase + (uint32_t)((mt * 16 * HPITCH + ks * 16) * 2));
#pragma unroll
            for (int np = 0; np < 2; np++)
                LDMX4(bf[2*np][0], bf[2*np][1], bf[2*np+1][0], bf[2*np+1][1],
                      bbase + (uint32_t)((np * 16 * HPITCH + ks * 16) * 2));
#pragma unroll
            for (int mt = 0; mt < 4; mt++)
#pragma unroll
                for (int nt = 0; nt < 4; nt++)
                    MMA16816(acc[mt][nt], af[mt], bf[nt]);
        }
    };

    // ---- 3-stage pipeline, one barrier per chunk ----
    issue_load(0, 0);
    issue_load(1, 1);
    for (int ci = 0; ci < NCH; ci++) {
        if (ci + 1 < NCH) CP_WAIT1(); else CP_WAIT0();
        __syncthreads();
        if (ci + 2 < NCH) issue_load(ci + 2, (ci + 2) % NSTAGE);
        compute(ci % NSTAGE);
    }

    // ---- epilogue ----
    OT* C;
    int cb;
    if (TAPS == 3 && bnb >= 4) { C = Ck; cb = bnb * NTILE - 512; }
    else                       { C = Cq; cb = bnb * NTILE; }
    const float* bp = bias + bnb * NTILE;

#pragma unroll
    for (int mt = 0; mt < 4; mt++) {
        const size_t rw = m0 + warpM + mt * 16 + r4;
#pragma unroll
        for (int nt = 0; nt < 4; nt++) {
            const int cl = warpN + nt * 8 + 2 * c2;
            const float bx = bp[cl], by = bp[cl + 1];
            float x0 = acc[mt][nt][0] + bx, y0 = acc[mt][nt][1] + by;
            float x1 = acc[mt][nt][2] + bx, y1 = acc[mt][nt][3] + by;
            if constexpr (sizeof(OT) == 2) {
                __half2 h0 = __floats2half2_rn(x0, y0);
                __half2 h1 = __floats2half2_rn(x1, y1);
                *(uint32_t*)((__half*)C + rw       * DD + cb + cl) = *(uint32_t*)&h0;
                *(uint32_t*)((__half*)C + (rw + 8) * DD + cb + cl) = *(uint32_t*)&h1;
            } else {
                *(float2*)((float*)C + rw       * DD + cb + cl) = make_float2(x0, y0);
                *(float2*)((float*)C + (rw + 8) * DD + cb + cl) = make_float2(x1, y1);
            }
        }
    }
}

// ---------------- tensor-core attention: one block per (b, n, h); 128 thr, T=64, DH=64 ----------------
#define APIT 72                                    // halves per smem row
#define ATTN_SMEM (3 * 64 * APIT * 2)              // 27648 B

__global__ void __launch_bounds__(128) attn_tc(
    const __half* __restrict__ Q, const __half* __restrict__ K,
    const __half* __restrict__ V, __half* __restrict__ O)
{
    extern __shared__ __align__(16) __half smh[];
    __half* Qs = smh;               // [64][APIT]
    __half* Ks = smh + 64 * APIT;
    __half* Vs = smh + 2 * 64 * APIT;

    const int tid  = threadIdx.x;
    const int lane = tid & 31;
    const int w    = tid >> 5;
    const int mat  = lane >> 3;
    const int r8   = lane & 7;
    const int qr   = lane >> 2;
    const int qc   = lane & 3;

    const int hid = blockIdx.x;
    const int h = hid & 7;
    const int n = (hid >> 3) & 127;
    const int b = hid >> 10;
    const size_t base = (((size_t)b * TT) * NV + n) * DD + h * DH;
    const size_t rstride = (size_t)NV * DD;

#pragma unroll
    for (int p = 0; p < 4; p++) {
        int idx = tid + 128 * p;
        int row = idx >> 3, q = idx & 7;
        size_t g = base + (size_t)row * rstride + q * 8;
        int so = row * APIT + q * 8;
        *(uint4*)(Qs + so) = *(const uint4*)(Q + g);
        *(uint4*)(Ks + so) = *(const uint4*)(K + g);
        *(uint4*)(Vs + so) = *(const uint4*)(V + g);
    }
    __syncthreads();

    const uint32_t sQ = smem_u32(Qs);
    const uint32_t sK = smem_u32(Ks);
    const uint32_t sV = smem_u32(Vs);

    // ---- S = Q K^T ----
    float acc[8][4];
#pragma unroll
    for (int nt = 0; nt < 8; nt++)
#pragma unroll
        for (int i = 0; i < 4; i++) acc[nt][i] = 0.f;

    const uint32_t aoff = sQ + (uint32_t)(((16 * w + ((mat & 1) << 3) + r8) * APIT + ((mat >> 1) << 3)) * 2);
    const uint32_t koff = sK + (uint32_t)(((((mat >> 1) << 3) + r8) * APIT + ((mat & 1) << 3)) * 2);

#pragma unroll
    for (int ks = 0; ks < 4; ks++) {
        uint32_t af[4], bf[8][2];
        LDMX4(af[0], af[1], af[2], af[3], aoff + (uint32_t)(ks * 32));
#pragma unroll
        for (int np = 0; np < 4; np++)
            LDMX4(bf[2*np][0], bf[2*np][1], bf[2*np+1][0], bf[2*np+1][1],
                  koff + (uint32_t)((np * 16 * APIT + ks * 16) * 2));
#pragma unroll
        for (int nt = 0; nt < 8; nt++)
            MMA16816(acc[nt], af, bf[nt]);
    }

    // ---- softmax (rows 16w+qr and +8) ----
    float mx0 = -1e30f, mx1 = -1e30f;
#pragma unroll
    for (int nt = 0; nt < 8; nt++) {
#pragma unroll
        for (int i = 0; i < 4; i++) acc[nt][i] *= 0.125f;
        mx0 = fmaxf(mx0, fmaxf(acc[nt][0], acc[nt][1]));
        mx1 = fmaxf(mx1, fmaxf(acc[nt][2], acc[nt][3]));
    }
    mx0 = fmaxf(mx0, __shfl_xor_sync(0xffffffff, mx0, 1));
    mx0 = fmaxf(mx0, __shfl_xor_sync(0xffffffff, mx0, 2));
    mx1 = fmaxf(mx1, __shfl_xor_sync(0xffffffff, mx1, 1));
    mx1 = fmaxf(mx1, __shfl_xor_sync(0xffffffff, mx1, 2));

    float sum0 = 0.f, sum1 = 0.f;
#pragma unroll
    for (int nt = 0; nt < 8; nt++) {
        acc[nt][0] = __expf(acc[nt][0] - mx0);
        acc[nt][1] = __expf(acc[nt][1] - mx0);
        acc[nt][2] = __expf(acc[nt][2] - mx1);
        acc[nt][3] = __expf(acc[nt][3] - mx1);
        sum0 += acc[nt][0] + acc[nt][1];
        sum1 += acc[nt][2] + acc[nt][3];
    }
    sum0 += __shfl_xor_sync(0xffffffff, sum0, 1);
    sum0 += __shfl_xor_sync(0xffffffff, sum0, 2);
    sum1 += __shfl_xor_sync(0xffffffff, sum1, 1);
    sum1 += __shfl_xor_sync(0xffffffff, sum1, 2);
    const float inv0 = 1.f / sum0, inv1 = 1.f / sum1;

    // ---- O = P V ----
    float acco[8][4];
#pragma unroll
    for (int nt = 0; nt < 8; nt++)
#pragma unroll
        for (int i = 0; i < 4; i++) acco[nt][i] = 0.f;

    const uint32_t voff = sV + (uint32_t)((((mat & 1) * 8 + r8) * APIT + ((mat >> 1) << 3)) * 2);

#pragma unroll
    for (int kt = 0; kt < 4; kt++) {
        uint32_t af[4];
        __half2 p0 = __floats2half2_rn(acc[2*kt][0]   * inv0, acc[2*kt][1]   * inv0);
        __half2 p1 = __floats2half2_rn(acc[2*kt][2]   * inv1, acc[2*kt][3]   * inv1);
        __half2 p2 = __floats2half2_rn(acc[2*kt+1][0] * inv0, acc[2*kt+1][1] * inv0);
        __half2 p3 = __floats2half2_rn(acc[2*kt+1][2] * inv1, acc[2*kt+1][3] * inv1);
        af[0] = *(uint32_t*)&p0; af[1] = *(uint32_t*)&p1;
        af[2] = *(uint32_t*)&p2; af[3] = *(uint32_t*)&p3;

#pragma unroll
        for (int dp = 0; dp < 4; dp++) {
            uint32_t bf0[2], bf1[2];
            LDMX4T(bf0[0], bf0[1], bf1[0], bf1[1],
                   voff + (uint32_t)((kt * 16 * APIT + dp * 16) * 2));
            MMA16816(acco[2*dp],     af, bf0);
            MMA16816(acco[2*dp + 1], af, bf1);
        }
    }

    const size_t row0 = base + (size_t)(16 * w + qr) * rstride;
    const size_t row1 = row0 + 8 * rstride;
#pragma unroll
    for (int nt = 0; nt < 8; nt++) {
        int col = nt * 8 + 2 * qc;
        __half2 h0 = __floats2half2_rn(acco[nt][0], acco[nt][1]);
        __half2 h1 = __floats2half2_rn(acco[nt][2], acco[nt][3]);
        *(uint32_t*)(O + row0 + col) = *(uint32_t*)&h0;
        *(uint32_t*)(O + row1 + col) = *(uint32_t*)&h1;
    }
}

// ---------------- launch ----------------
extern "C" void kernel_launch(void* const* d_in, const int* in_sizes, int n_in,
                              void* d_out, int out_size)
{
    const float* X     = (const float*)d_in[0];
    const float* Wq    = (const float*)d_in[1];
    const float* bq    = (const float*)d_in[2];
    const float* gq    = (const float*)d_in[3];
    const float* betaq = (const float*)d_in[4];
    const float* mq    = (const float*)d_in[5];
    const float* vq    = (const float*)d_in[6];
    const float* Wk    = (const float*)d_in[7];
    const float* bk    = (const float*)d_in[8];
    const float* gk    = (const float*)d_in[9];
    const float* betak = (const float*)d_in[10];
    const float* mk    = (const float*)d_in[11];
    const float* vk    = (const float*)d_in[12];
    const float* Wv    = (const float*)d_in[13];
    const float* bv    = (const float*)d_in[14];
    const float* Wo    = (const float*)d_in[15];
    const float* bo    = (const float*)d_in[16];
    float* out = (float*)d_out;

    __half *p_xh, *p_qh, *p_kh, *p_vh, *p_ao, *p_wqk, *p_wv, *p_wo;
    float *p_bqk;
    cudaGetSymbolAddress((void**)&p_xh,  g_xh);
    cudaGetSymbolAddress((void**)&p_qh,  g_qh);
    cudaGetSymbolAddress((void**)&p_kh,  g_kh);
    cudaGetSymbolAddress((void**)&p_vh,  g_vh);
    cudaGetSymbolAddress((void**)&p_ao,  g_ao);
    cudaGetSymbolAddress((void**)&p_wqk, g_wqk);
    cudaGetSymbolAddress((void**)&p_wv,  g_wv);
    cudaGetSymbolAddress((void**)&p_wo,  g_wo);
    cudaGetSymbolAddress((void**)&p_bqk, g_bqk);

    // 1) fp16 operand prep
    x_to_half<<<(MM * DD / 8 + 255) / 256, 256>>>(X, p_xh);
    prep_weights<<<(R3 + 255) / 256, 256>>>(Wq, gq, vq, Wk, gk, vk, Wv, Wo,
                                            bq, betaq, mq, bk, betak, mk,
                                            p_wqk, p_wv, p_wo, p_bqk);

    // 2) projections (fp16 tensor cores, 512 threads / 16 warps per CTA)
    cudaFuncSetAttribute(gemm_h<3, __half>, cudaFuncAttributeMaxDynamicSharedMemorySize, GEMM_SMEM);
    cudaFuncSetAttribute(gemm_h<1, __half>, cudaFuncAttributeMaxDynamicSharedMemorySize, GEMM_SMEM);
    cudaFuncSetAttribute(gemm_h<1, float>,  cudaFuncAttributeMaxDynamicSharedMemorySize, GEMM_SMEM);
    dim3 gqk(1024 / NTILE, MM / MTILE);   // (8, 256) — fused Q+K
    dim3 gl (DD / NTILE,   MM / MTILE);   // (4, 256)
    gemm_h<3, __half><<<gqk, GTHREADS, GEMM_SMEM>>>(p_xh, p_wqk, p_bqk, p_qh, p_kh);
    gemm_h<1, __half><<<gl,  GTHREADS, GEMM_SMEM>>>(p_xh, p_wv, bv, p_vh, nullptr);

    // 3) tensor-core attention (8192 heads)
    cudaFuncSetAttribute(attn_tc, cudaFuncAttributeMaxDynamicSharedMemorySize, ATTN_SMEM);
    attn_tc<<<BB * NV * KH, 128, ATTN_SMEM>>>(p_qh, p_kh, p_vh, p_ao);

    // 4) output projection -> d_out (fp32)
    gemm_h<1, float><<<gl, GTHREADS, GEMM_SMEM>>>(p_ao, p_wo, bo, out, nullptr);
}